// round 1
// baseline (speedup 1.0000x reference)
#include <cuda_runtime.h>
#include <math.h>

// Problem constants
#define B_   2
#define T_   2048
#define C_   2048
#define NH   16
#define NKV  8
#define HD   128
#define KVD  (NKV*HD)          // 1024
#define QKV_DIM (C_ + 2*KVD)   // 4096
#define EPS_ 1.1920929e-07f
#define SCALE_ 0.08838834764831845f   // 1/sqrt(128)

// Scratch (static device globals — allocation-free per harness rules)
__device__ float g_qkv[(size_t)B_*T_*QKV_DIM];   // 64 MB
__device__ float g_q[(size_t)B_*NH*T_*HD];       // 32 MB
__device__ float g_k[(size_t)B_*NKV*T_*HD];      // 16 MB
__device__ float g_v[(size_t)B_*NKV*T_*HD];      // 16 MB
__device__ float g_y[(size_t)B_*T_*C_];          // 32 MB

// ---------------------------------------------------------------------------
// GEMM (NT): C[m,n] = sum_k A[m,k] * B[n,k]; A row-major [M,K], B row-major [N,K]
// 128x128 tile, BK=8, 8x8 per thread, 256 threads.
// ---------------------------------------------------------------------------
__global__ __launch_bounds__(256) void gemm_nt_kernel(
    const float* __restrict__ A, const float* __restrict__ Bm,
    float* __restrict__ C, int M, int N, int K)
{
    __shared__ float As[8][128];
    __shared__ float Bs[8][128];
    int tid = threadIdx.x;
    int tr  = tid >> 4;        // 0..15
    int tc  = tid & 15;        // 0..15
    int m0  = blockIdx.y * 128;
    int n0  = blockIdx.x * 128;
    int arow = tid >> 1;       // 0..127
    int acol = (tid & 1) * 4;  // 0 or 4

    float acc[8][8];
#pragma unroll
    for (int i = 0; i < 8; i++)
#pragma unroll
        for (int j = 0; j < 8; j++) acc[i][j] = 0.f;

    const float* Ab = A + (size_t)m0 * K;
    const float* Bb = Bm + (size_t)n0 * K;

    for (int k0 = 0; k0 < K; k0 += 8) {
        float4 a4 = *(const float4*)(Ab + (size_t)arow * K + k0 + acol);
        float4 b4 = *(const float4*)(Bb + (size_t)arow * K + k0 + acol);
        As[acol + 0][arow] = a4.x; As[acol + 1][arow] = a4.y;
        As[acol + 2][arow] = a4.z; As[acol + 3][arow] = a4.w;
        Bs[acol + 0][arow] = b4.x; Bs[acol + 1][arow] = b4.y;
        Bs[acol + 2][arow] = b4.z; Bs[acol + 3][arow] = b4.w;
        __syncthreads();
#pragma unroll
        for (int kk = 0; kk < 8; kk++) {
            float ra[8], rb[8];
            *(float4*)&ra[0] = *(const float4*)&As[kk][tr * 8];
            *(float4*)&ra[4] = *(const float4*)&As[kk][tr * 8 + 4];
            *(float4*)&rb[0] = *(const float4*)&Bs[kk][tc * 8];
            *(float4*)&rb[4] = *(const float4*)&Bs[kk][tc * 8 + 4];
#pragma unroll
            for (int i = 0; i < 8; i++)
#pragma unroll
                for (int j = 0; j < 8; j++)
                    acc[i][j] += ra[i] * rb[j];
        }
        __syncthreads();
    }

#pragma unroll
    for (int i = 0; i < 8; i++) {
        float* cp = C + (size_t)(m0 + tr * 8 + i) * N + n0 + tc * 8;
        *(float4*)cp       = make_float4(acc[i][0], acc[i][1], acc[i][2], acc[i][3]);
        *(float4*)(cp + 4) = make_float4(acc[i][4], acc[i][5], acc[i][6], acc[i][7]);
    }
}

// ---------------------------------------------------------------------------
// RoPE + RMSnorm + layout change. Block = one (b,t), 256 threads = 8 warps.
// Lane j of a warp holds head elements {j, j+32, j+64, j+96}, so rotate-half
// pairs (d, d+64) are in-lane. Warp shfl reduction for RMS.
// Writes q[b,h,t,d], k[b,kvh,t,d], v[b,kvh,t,d].
// ---------------------------------------------------------------------------
__global__ __launch_bounds__(256) void rope_rms_kernel(
    const float* __restrict__ cosb, const float* __restrict__ sinb)
{
    int bt = blockIdx.x;
    int b = bt / T_, t = bt % T_;
    int warp = threadIdx.x >> 5, lane = threadIdx.x & 31;
    const float* base = g_qkv + (size_t)bt * QKV_DIM;

    float c0 = cosb[t * 64 + lane],      c1 = cosb[t * 64 + lane + 32];
    float s0 = sinb[t * 64 + lane],      s1 = sinb[t * 64 + lane + 32];

    for (int hh = warp; hh < NH + NKV; hh += 8) {
        const float* src;
        float* dst;
        if (hh < NH) {
            src = base + hh * HD;
            dst = g_q + ((size_t)(b * NH + hh) * T_ + t) * HD;
        } else {
            int kv = hh - NH;
            src = base + C_ + kv * HD;
            dst = g_k + ((size_t)(b * NKV + kv) * T_ + t) * HD;
        }
        float v0 = src[lane], v1 = src[lane + 32], v2 = src[lane + 64], v3 = src[lane + 96];
        float y0 =  v0 * c0 + v2 * s0;
        float y2 = -v0 * s0 + v2 * c0;
        float y1 =  v1 * c1 + v3 * s1;
        float y3 = -v1 * s1 + v3 * c1;
        float ss = y0 * y0 + y1 * y1 + y2 * y2 + y3 * y3;
#pragma unroll
        for (int o = 16; o > 0; o >>= 1) ss += __shfl_xor_sync(0xffffffffu, ss, o);
        float r = rsqrtf(ss * (1.0f / HD) + EPS_);
        dst[lane]      = y0 * r;
        dst[lane + 32] = y1 * r;
        dst[lane + 64] = y2 * r;
        dst[lane + 96] = y3 * r;
    }
    // V copy (8 kv heads, one per warp)
    {
        int kv = warp;
        const float4* src = (const float4*)(base + C_ + KVD + kv * HD);
        float4* dst = (float4*)(g_v + ((size_t)(b * NKV + kv) * T_ + t) * HD);
        dst[lane] = src[lane];
    }
}

// ---------------------------------------------------------------------------
// Flash attention, causal, fp32, GQA (h -> kv head h/2).
// Block = (q_tile of 64, head, batch), 256 threads as 16x16 grid.
// Score micro-tile 4x4 per thread; output micro-tile 4 rows x 8 d-cols
// with d = tx + 16*k (conflict-free V reads).
// SMEM strides padded: QS/KS/VS stride 129 (odd -> <=2-way), PS stride 65.
// ---------------------------------------------------------------------------
#define BQ 64
#define BKT 64
#define QSS 129
#define PSS 65
#define ATTN_SMEM ((3 * BKT * QSS + BQ * PSS) * 4)

__global__ __launch_bounds__(256) void attn_kernel()
{
    extern __shared__ float sm[];
    float* Qs = sm;
    float* Ks = Qs + BQ * QSS;
    float* Vs = Ks + BKT * QSS;
    float* Ps = Vs + BKT * QSS;

    int qt = blockIdx.x, h = blockIdx.y, b = blockIdx.z;
    int kvh = h >> 1;
    int tid = threadIdx.x;
    int ty = tid >> 4, tx = tid & 15;

    const float* qptr = g_q + ((size_t)(b * NH + h) * T_) * HD;
    const float* kptr = g_k + ((size_t)(b * NKV + kvh) * T_) * HD;
    const float* vptr = g_v + ((size_t)(b * NKV + kvh) * T_) * HD;
    int q0 = qt * BQ;

    // Load Q tile (pre-scaled)
    for (int i = tid; i < BQ * HD; i += 256) {
        int r = i >> 7, c = i & 127;
        Qs[r * QSS + c] = qptr[(size_t)(q0 + r) * HD + c] * SCALE_;
    }

    float m[4], l[4], acc[4][8];
#pragma unroll
    for (int i = 0; i < 4; i++) {
        m[i] = -1e30f; l[i] = 0.f;
#pragma unroll
        for (int j = 0; j < 8; j++) acc[i][j] = 0.f;
    }

    for (int kt = 0; kt <= qt; kt++) {
        int k0 = kt * BKT;
        // Load K,V tiles
        for (int i = tid; i < BKT * HD; i += 256) {
            int r = i >> 7, c = i & 127;
            Ks[r * QSS + c] = kptr[(size_t)(k0 + r) * HD + c];
            Vs[r * QSS + c] = vptr[(size_t)(k0 + r) * HD + c];
        }
        __syncthreads();

        // S = Q K^T (64x64), 4x4 per thread
        float s[4][4];
#pragma unroll
        for (int i = 0; i < 4; i++)
#pragma unroll
            for (int j = 0; j < 4; j++) s[i][j] = 0.f;

#pragma unroll 4
        for (int d = 0; d < HD; d++) {
            float ra[4], rb[4];
#pragma unroll
            for (int i = 0; i < 4; i++) ra[i] = Qs[(ty * 4 + i) * QSS + d];
#pragma unroll
            for (int j = 0; j < 4; j++) rb[j] = Ks[(tx * 4 + j) * QSS + d];
#pragma unroll
            for (int i = 0; i < 4; i++)
#pragma unroll
                for (int j = 0; j < 4; j++)
                    s[i][j] += ra[i] * rb[j];
        }

        // Causal mask on diagonal tile
        if (kt == qt) {
#pragma unroll
            for (int i = 0; i < 4; i++) {
                int ig = ty * 4 + i;
#pragma unroll
                for (int j = 0; j < 4; j++)
                    if (tx * 4 + j > ig) s[i][j] = -1e30f;
            }
        }

        // Online softmax update (row reductions across 16-lane tx groups)
#pragma unroll
        for (int i = 0; i < 4; i++) {
            float mr = fmaxf(fmaxf(s[i][0], s[i][1]), fmaxf(s[i][2], s[i][3]));
#pragma unroll
            for (int o = 8; o > 0; o >>= 1)
                mr = fmaxf(mr, __shfl_xor_sync(0xffffffffu, mr, o));
            float mnew = fmaxf(m[i], mr);
            float p0 = __expf(s[i][0] - mnew);
            float p1 = __expf(s[i][1] - mnew);
            float p2 = __expf(s[i][2] - mnew);
            float p3 = __expf(s[i][3] - mnew);
            float ladd = p0 + p1 + p2 + p3;
#pragma unroll
            for (int o = 8; o > 0; o >>= 1)
                ladd += __shfl_xor_sync(0xffffffffu, ladd, o);
            float f = __expf(m[i] - mnew);
            l[i] = l[i] * f + ladd;
            m[i] = mnew;
#pragma unroll
            for (int j = 0; j < 8; j++) acc[i][j] *= f;
            int prow = (ty * 4 + i) * PSS + tx * 4;
            Ps[prow + 0] = p0; Ps[prow + 1] = p1; Ps[prow + 2] = p2; Ps[prow + 3] = p3;
        }
        __syncthreads();

        // O += P V : each thread d-cols = tx + 16*k
        for (int j = 0; j < BKT; j++) {
            float rv[8];
#pragma unroll
            for (int d8 = 0; d8 < 8; d8++) rv[d8] = Vs[j * QSS + tx + 16 * d8];
#pragma unroll
            for (int i = 0; i < 4; i++) {
                float p = Ps[(ty * 4 + i) * PSS + j];
#pragma unroll
                for (int d8 = 0; d8 < 8; d8++) acc[i][d8] += p * rv[d8];
            }
        }
        __syncthreads();
    }

    // Write y[b, t, h*128 + d]
#pragma unroll
    for (int i = 0; i < 4; i++) {
        float inv = 1.0f / l[i];
        int trow = q0 + ty * 4 + i;
        float* yp = g_y + ((size_t)(b * T_) + trow) * C_ + h * HD;
#pragma unroll
        for (int d8 = 0; d8 < 8; d8++)
            yp[tx + 16 * d8] = acc[i][d8] * inv;
    }
}

// ---------------------------------------------------------------------------
// Launch: qkv gemm -> rope/rms -> attention -> out proj
// Inputs (metadata order): x, w_attn, w_proj, cos, sin. Output float32.
// ---------------------------------------------------------------------------
extern "C" void kernel_launch(void* const* d_in, const int* in_sizes, int n_in,
                              void* d_out, int out_size)
{
    const float* x      = (const float*)d_in[0];
    const float* w_attn = (const float*)d_in[1];
    const float* w_proj = (const float*)d_in[2];
    const float* cosb   = (const float*)d_in[3];
    const float* sinb   = (const float*)d_in[4];
    float* out = (float*)d_out;

    void *p_qkv, *p_y;
    cudaGetSymbolAddress(&p_qkv, g_qkv);
    cudaGetSymbolAddress(&p_y, g_y);

    cudaFuncSetAttribute(attn_kernel, cudaFuncAttributeMaxDynamicSharedMemorySize, ATTN_SMEM);

    dim3 g1(QKV_DIM / 128, (B_ * T_) / 128);
    gemm_nt_kernel<<<g1, 256>>>(x, w_attn, (float*)p_qkv, B_ * T_, QKV_DIM, C_);

    rope_rms_kernel<<<B_ * T_, 256>>>(cosb, sinb);

    dim3 ga(T_ / BQ, NH, B_);
    attn_kernel<<<ga, 256, ATTN_SMEM>>>();

    dim3 g2(C_ / 128, (B_ * T_) / 128);
    gemm_nt_kernel<<<g2, 256>>>((const float*)p_y, w_proj, out, B_ * T_, C_, C_);
}

// round 4
// speedup vs baseline: 1.8541x; 1.8541x over previous
#include <cuda_runtime.h>
#include <cuda_bf16.h>
#include <cstdint>
#include <math.h>

// Problem constants
#define B_   2
#define T_   2048
#define C_   2048
#define NH   16
#define NKV  8
#define HD   128
#define KVD  (NKV*HD)          // 1024
#define QKV_DIM (C_ + 2*KVD)   // 4096
#define EPS_ 1.1920929e-07f
#define SCALE_ 0.08838834764831845f   // 1/sqrt(128)

// ---------------- scratch (static device globals; allocation-free) ----------
__device__ float g_qkv[(size_t)B_*T_*QKV_DIM];   // 64 MB
__device__ float g_q[(size_t)B_*NH*T_*HD];       // 32 MB
__device__ float g_k[(size_t)B_*NKV*T_*HD];      // 16 MB
__device__ float g_v[(size_t)B_*NKV*T_*HD];      // 16 MB
__device__ float g_y[(size_t)B_*T_*C_];          // 32 MB
// bf16 hi/lo planes
__device__ __nv_bfloat16 g_xhi[(size_t)B_*T_*C_];
__device__ __nv_bfloat16 g_xlo[(size_t)B_*T_*C_];
__device__ __nv_bfloat16 g_wahi[(size_t)QKV_DIM*C_];
__device__ __nv_bfloat16 g_walo[(size_t)QKV_DIM*C_];
__device__ __nv_bfloat16 g_wphi[(size_t)C_*C_];
__device__ __nv_bfloat16 g_wplo[(size_t)C_*C_];
__device__ __nv_bfloat16 g_yhi[(size_t)B_*T_*C_];
__device__ __nv_bfloat16 g_ylo[(size_t)B_*T_*C_];

// ---------------------------------------------------------------------------
// helpers
// ---------------------------------------------------------------------------
__device__ __forceinline__ uint32_t smem_u32(const void* p) {
    uint32_t a;
    asm("{ .reg .u64 t; cvta.to.shared.u64 t, %1; cvt.u32.u64 %0, t; }" : "=r"(a) : "l"(p));
    return a;
}
__device__ __forceinline__ void cp_async16(uint32_t dst, const void* src) {
    asm volatile("cp.async.cg.shared.global [%0], [%1], 16;" :: "r"(dst), "l"(src));
}
__device__ __forceinline__ void cp_commit() {
    asm volatile("cp.async.commit_group;");
}
__device__ __forceinline__ void cp_wait1() {
    asm volatile("cp.async.wait_group 1;");
}
__device__ __forceinline__ void cp_wait0() {
    asm volatile("cp.async.wait_group 0;");
}
__device__ __forceinline__ void ldm_x4(uint32_t& r0, uint32_t& r1, uint32_t& r2, uint32_t& r3, uint32_t a) {
    asm volatile("ldmatrix.sync.aligned.m8n8.x4.shared.b16 {%0,%1,%2,%3}, [%4];"
                 : "=r"(r0), "=r"(r1), "=r"(r2), "=r"(r3) : "r"(a));
}
__device__ __forceinline__ void mma_bf16(float* d, const uint32_t* a, const uint32_t* b) {
    asm volatile(
        "mma.sync.aligned.m16n8k16.row.col.f32.bf16.bf16.f32 "
        "{%0,%1,%2,%3}, {%4,%5,%6,%7}, {%8,%9}, {%0,%1,%2,%3};"
        : "+f"(d[0]), "+f"(d[1]), "+f"(d[2]), "+f"(d[3])
        : "r"(a[0]), "r"(a[1]), "r"(a[2]), "r"(a[3]), "r"(b[0]), "r"(b[1]));
}
// swizzled byte offset for row r (64B/row), 16B chunk c (0..3):
// conflict-free for cp.async stores and ldmatrix 8-row phases
__device__ __forceinline__ uint32_t swz(int r, int c) {
    return (uint32_t)(r * 64 + ((c ^ ((r >> 1) & 3)) << 4));
}

// ---------------------------------------------------------------------------
// split fp32 -> (hi, lo) bf16 planes
// ---------------------------------------------------------------------------
__global__ __launch_bounds__(256) void split_bf16_kernel(
    const float* __restrict__ in, __nv_bfloat16* __restrict__ hi,
    __nv_bfloat16* __restrict__ lo, int n4)
{
    int i = blockIdx.x * blockDim.x + threadIdx.x;
    if (i >= n4) return;
    float4 v = ((const float4*)in)[i];
    __nv_bfloat16 h0 = __float2bfloat16(v.x);
    __nv_bfloat16 h1 = __float2bfloat16(v.y);
    __nv_bfloat16 h2 = __float2bfloat16(v.z);
    __nv_bfloat16 h3 = __float2bfloat16(v.w);
    __nv_bfloat16 l0 = __float2bfloat16(v.x - __bfloat162float(h0));
    __nv_bfloat16 l1 = __float2bfloat16(v.y - __bfloat162float(h1));
    __nv_bfloat16 l2 = __float2bfloat16(v.z - __bfloat162float(h2));
    __nv_bfloat16 l3 = __float2bfloat16(v.w - __bfloat162float(h3));
    __nv_bfloat162 ha, hb, la, lb;
    ha.x = h0; ha.y = h1; hb.x = h2; hb.y = h3;
    la.x = l0; la.y = l1; lb.x = l2; lb.y = l3;
    ((__nv_bfloat162*)hi)[2 * i]     = ha;
    ((__nv_bfloat162*)hi)[2 * i + 1] = hb;
    ((__nv_bfloat162*)lo)[2 * i]     = la;
    ((__nv_bfloat162*)lo)[2 * i + 1] = lb;
}

// ---------------------------------------------------------------------------
// bf16 split GEMM (NT) via mma.sync: C[m,n] = sum_k A[m,k]*B[n,k], fp32 acc.
// 3 passes: Ahi*Bhi + Ahi*Blo + Alo*Bhi, accumulated in registers.
// Tile 128x128, BK=32, 256 threads = 8 warps (2x4), warp tile 64x32.
// cp.async double-buffered SMEM with swizzle.
// ---------------------------------------------------------------------------
__global__ __launch_bounds__(256, 2) void gemm_mma_kernel(
    const __nv_bfloat16* __restrict__ Ahi, const __nv_bfloat16* __restrict__ Alo,
    const __nv_bfloat16* __restrict__ Bhi, const __nv_bfloat16* __restrict__ Blo,
    float* __restrict__ C, int M, int N, int K)
{
    __shared__ __align__(128) unsigned char smem_raw[4 * 8192]; // sA[2], sB[2]
    uint32_t sb = smem_u32(smem_raw);

    int tid = threadIdx.x;
    int wid = tid >> 5, lane = tid & 31;
    int wm = wid >> 2, wn = wid & 3;      // warp grid 2x4
    int m0 = blockIdx.y * 128, n0 = blockIdx.x * 128;

    int grp = lane >> 2, qid = lane & 3;  // mma fragment indices

    float acc[4][4][4];
#pragma unroll
    for (int mi = 0; mi < 4; mi++)
#pragma unroll
        for (int ni = 0; ni < 4; ni++)
#pragma unroll
            for (int r = 0; r < 4; r++) acc[mi][ni][r] = 0.f;

    int kcpp = K >> 5;       // BK=32 chunks per pass
    int nch = 3 * kcpp;

    // per-thread load assignment: 2 chunks of A, 2 of B per tile
    int r0_ = tid >> 2, c0_ = tid & 3;          // idx = tid
    int r1_ = (tid + 256) >> 2, c1_ = tid & 3;  // idx = tid + 256 (same c)

    // issue tile c into buffer c&1
    auto issue = [&](int c) {
        int pass = c / kcpp, kc = c - pass * kcpp;
        const __nv_bfloat16* Ap = (pass == 2) ? Alo : Ahi;
        const __nv_bfloat16* Bp = (pass == 1) ? Blo : Bhi;
        int kofs = kc << 5;
        int s = c & 1;
        uint32_t aB = sb + s * 8192;
        uint32_t bB = sb + 16384 + s * 8192;
        cp_async16(aB + swz(r0_, c0_), Ap + (size_t)(m0 + r0_) * K + kofs + c0_ * 8);
        cp_async16(aB + swz(r1_, c1_), Ap + (size_t)(m0 + r1_) * K + kofs + c1_ * 8);
        cp_async16(bB + swz(r0_, c0_), Bp + (size_t)(n0 + r0_) * K + kofs + c0_ * 8);
        cp_async16(bB + swz(r1_, c1_), Bp + (size_t)(n0 + r1_) * K + kofs + c1_ * 8);
        cp_commit();
    };

    issue(0);

    // ldmatrix lane address components (same formula for A and B)
    int lrow_add = (lane & 7) + (((lane >> 3) & 1) << 3);  // 0..15
    int lchunk_add = lane >> 4;                             // 0 or 1

    for (int c = 0; c < nch; c++) {
        bool have_next = (c + 1 < nch);
        if (have_next) issue(c + 1);
        if (have_next) cp_wait1(); else cp_wait0();
        __syncthreads();

        int s = c & 1;
        uint32_t aB = sb + s * 8192;
        uint32_t bB = sb + 16384 + s * 8192;

#pragma unroll
        for (int ks = 0; ks < 2; ks++) {
            int cbase = ks * 2 + lchunk_add;
            uint32_t af[4][4];
#pragma unroll
            for (int mi = 0; mi < 4; mi++) {
                int row = wm * 64 + mi * 16 + lrow_add;
                ldm_x4(af[mi][0], af[mi][1], af[mi][2], af[mi][3], aB + swz(row, cbase));
            }
            uint32_t bf[4][2];
#pragma unroll
            for (int p = 0; p < 2; p++) {
                int row = wn * 32 + p * 16 + lrow_add;
                uint32_t t0, t1, t2, t3;
                ldm_x4(t0, t1, t2, t3, bB + swz(row, cbase));
                bf[p * 2][0] = t0;     bf[p * 2][1] = t2;
                bf[p * 2 + 1][0] = t1; bf[p * 2 + 1][1] = t3;
            }
#pragma unroll
            for (int mi = 0; mi < 4; mi++)
#pragma unroll
                for (int ni = 0; ni < 4; ni++)
                    mma_bf16(acc[mi][ni], af[mi], bf[ni]);
        }
        __syncthreads();
    }

    // epilogue: C[m0 + wm*64 + mi*16 + grp(+8)][n0 + wn*32 + ni*8 + qid*2(+1)]
#pragma unroll
    for (int mi = 0; mi < 4; mi++) {
        int rbase = m0 + wm * 64 + mi * 16 + grp;
#pragma unroll
        for (int ni = 0; ni < 4; ni++) {
            int col = n0 + wn * 32 + ni * 8 + qid * 2;
            float* p0 = C + (size_t)rbase * N + col;
            float* p1 = C + (size_t)(rbase + 8) * N + col;
            p0[0] = acc[mi][ni][0]; p0[1] = acc[mi][ni][1];
            p1[0] = acc[mi][ni][2]; p1[1] = acc[mi][ni][3];
        }
    }
}

// ---------------------------------------------------------------------------
// RoPE + RMSnorm + layout change
// ---------------------------------------------------------------------------
__global__ __launch_bounds__(256) void rope_rms_kernel(
    const float* __restrict__ cosb, const float* __restrict__ sinb)
{
    int bt = blockIdx.x;
    int b = bt / T_, t = bt % T_;
    int warp = threadIdx.x >> 5, lane = threadIdx.x & 31;
    const float* base = g_qkv + (size_t)bt * QKV_DIM;

    float c0 = cosb[t * 64 + lane], c1 = cosb[t * 64 + lane + 32];
    float s0 = sinb[t * 64 + lane], s1 = sinb[t * 64 + lane + 32];

    for (int hh = warp; hh < NH + NKV; hh += 8) {
        const float* src;
        float* dst;
        if (hh < NH) {
            src = base + hh * HD;
            dst = g_q + ((size_t)(b * NH + hh) * T_ + t) * HD;
        } else {
            int kv = hh - NH;
            src = base + C_ + kv * HD;
            dst = g_k + ((size_t)(b * NKV + kv) * T_ + t) * HD;
        }
        float v0 = src[lane], v1 = src[lane + 32], v2 = src[lane + 64], v3 = src[lane + 96];
        float y0 =  v0 * c0 + v2 * s0;
        float y2 = -v0 * s0 + v2 * c0;
        float y1 =  v1 * c1 + v3 * s1;
        float y3 = -v1 * s1 + v3 * c1;
        float ss = y0 * y0 + y1 * y1 + y2 * y2 + y3 * y3;
#pragma unroll
        for (int o = 16; o > 0; o >>= 1) ss += __shfl_xor_sync(0xffffffffu, ss, o);
        float r = rsqrtf(ss * (1.0f / HD) + EPS_);
        dst[lane]      = y0 * r;
        dst[lane + 32] = y1 * r;
        dst[lane + 64] = y2 * r;
        dst[lane + 96] = y3 * r;
    }
    {
        int kv = warp;
        const float4* src = (const float4*)(base + C_ + KVD + kv * HD);
        float4* dst = (float4*)(g_v + ((size_t)(b * NKV + kv) * T_ + t) * HD);
        dst[lane] = src[lane];
    }
}

// ---------------------------------------------------------------------------
// Flash attention, causal, fp32, GQA
// ---------------------------------------------------------------------------
#define BQ 64
#define BKT 64
#define QSS 129
#define PSS 65
#define ATTN_SMEM ((3 * BKT * QSS + BQ * PSS) * 4)

__global__ __launch_bounds__(256) void attn_kernel()
{
    extern __shared__ float sm[];
    float* Qs = sm;
    float* Ks = Qs + BQ * QSS;
    float* Vs = Ks + BKT * QSS;
    float* Ps = Vs + BKT * QSS;

    int qt = blockIdx.x, h = blockIdx.y, b = blockIdx.z;
    int kvh = h >> 1;
    int tid = threadIdx.x;
    int ty = tid >> 4, tx = tid & 15;

    const float* qptr = g_q + ((size_t)(b * NH + h) * T_) * HD;
    const float* kptr = g_k + ((size_t)(b * NKV + kvh) * T_) * HD;
    const float* vptr = g_v + ((size_t)(b * NKV + kvh) * T_) * HD;
    int q0 = qt * BQ;

    for (int i = tid; i < BQ * HD; i += 256) {
        int r = i >> 7, c = i & 127;
        Qs[r * QSS + c] = qptr[(size_t)(q0 + r) * HD + c] * SCALE_;
    }

    float m[4], l[4], acc[4][8];
#pragma unroll
    for (int i = 0; i < 4; i++) {
        m[i] = -1e30f; l[i] = 0.f;
#pragma unroll
        for (int j = 0; j < 8; j++) acc[i][j] = 0.f;
    }

    for (int kt = 0; kt <= qt; kt++) {
        int k0 = kt * BKT;
        for (int i = tid; i < BKT * HD; i += 256) {
            int r = i >> 7, c = i & 127;
            Ks[r * QSS + c] = kptr[(size_t)(k0 + r) * HD + c];
            Vs[r * QSS + c] = vptr[(size_t)(k0 + r) * HD + c];
        }
        __syncthreads();

        float s[4][4];
#pragma unroll
        for (int i = 0; i < 4; i++)
#pragma unroll
            for (int j = 0; j < 4; j++) s[i][j] = 0.f;

#pragma unroll 4
        for (int d = 0; d < HD; d++) {
            float ra[4], rb[4];
#pragma unroll
            for (int i = 0; i < 4; i++) ra[i] = Qs[(ty * 4 + i) * QSS + d];
#pragma unroll
            for (int j = 0; j < 4; j++) rb[j] = Ks[(tx * 4 + j) * QSS + d];
#pragma unroll
            for (int i = 0; i < 4; i++)
#pragma unroll
                for (int j = 0; j < 4; j++)
                    s[i][j] += ra[i] * rb[j];
        }

        if (kt == qt) {
#pragma unroll
            for (int i = 0; i < 4; i++) {
                int ig = ty * 4 + i;
#pragma unroll
                for (int j = 0; j < 4; j++)
                    if (tx * 4 + j > ig) s[i][j] = -1e30f;
            }
        }

#pragma unroll
        for (int i = 0; i < 4; i++) {
            float mr = fmaxf(fmaxf(s[i][0], s[i][1]), fmaxf(s[i][2], s[i][3]));
#pragma unroll
            for (int o = 8; o > 0; o >>= 1)
                mr = fmaxf(mr, __shfl_xor_sync(0xffffffffu, mr, o));
            float mnew = fmaxf(m[i], mr);
            float p0 = __expf(s[i][0] - mnew);
            float p1 = __expf(s[i][1] - mnew);
            float p2 = __expf(s[i][2] - mnew);
            float p3 = __expf(s[i][3] - mnew);
            float ladd = p0 + p1 + p2 + p3;
#pragma unroll
            for (int o = 8; o > 0; o >>= 1)
                ladd += __shfl_xor_sync(0xffffffffu, ladd, o);
            float f = __expf(m[i] - mnew);
            l[i] = l[i] * f + ladd;
            m[i] = mnew;
#pragma unroll
            for (int j = 0; j < 8; j++) acc[i][j] *= f;
            int prow = (ty * 4 + i) * PSS + tx * 4;
            Ps[prow + 0] = p0; Ps[prow + 1] = p1; Ps[prow + 2] = p2; Ps[prow + 3] = p3;
        }
        __syncthreads();

        for (int j = 0; j < BKT; j++) {
            float rv[8];
#pragma unroll
            for (int d8 = 0; d8 < 8; d8++) rv[d8] = Vs[j * QSS + tx + 16 * d8];
#pragma unroll
            for (int i = 0; i < 4; i++) {
                float p = Ps[(ty * 4 + i) * PSS + j];
#pragma unroll
                for (int d8 = 0; d8 < 8; d8++) acc[i][d8] += p * rv[d8];
            }
        }
        __syncthreads();
    }

#pragma unroll
    for (int i = 0; i < 4; i++) {
        float inv = 1.0f / l[i];
        int trow = q0 + ty * 4 + i;
        float* yp = g_y + ((size_t)(b * T_) + trow) * C_ + h * HD;
#pragma unroll
        for (int d8 = 0; d8 < 8; d8++)
            yp[tx + 16 * d8] = acc[i][d8] * inv;
    }
}

// ---------------------------------------------------------------------------
// Launch pipeline
// ---------------------------------------------------------------------------
extern "C" void kernel_launch(void* const* d_in, const int* in_sizes, int n_in,
                              void* d_out, int out_size)
{
    const float* x      = (const float*)d_in[0];
    const float* w_attn = (const float*)d_in[1];
    const float* w_proj = (const float*)d_in[2];
    const float* cosb   = (const float*)d_in[3];
    const float* sinb   = (const float*)d_in[4];
    float* out = (float*)d_out;

    void *p_qkv, *p_y, *p_xhi, *p_xlo, *p_wahi, *p_walo, *p_wphi, *p_wplo, *p_yhi, *p_ylo;
    cudaGetSymbolAddress(&p_qkv, g_qkv);
    cudaGetSymbolAddress(&p_y, g_y);
    cudaGetSymbolAddress(&p_xhi, g_xhi);  cudaGetSymbolAddress(&p_xlo, g_xlo);
    cudaGetSymbolAddress(&p_wahi, g_wahi); cudaGetSymbolAddress(&p_walo, g_walo);
    cudaGetSymbolAddress(&p_wphi, g_wphi); cudaGetSymbolAddress(&p_wplo, g_wplo);
    cudaGetSymbolAddress(&p_yhi, g_yhi);  cudaGetSymbolAddress(&p_ylo, g_ylo);

    cudaFuncSetAttribute(attn_kernel, cudaFuncAttributeMaxDynamicSharedMemorySize, ATTN_SMEM);

    // split inputs into bf16 hi/lo planes
    int n4x = (B_ * T_ * C_) / 4;
    split_bf16_kernel<<<(n4x + 255) / 256, 256>>>(x, (__nv_bfloat16*)p_xhi, (__nv_bfloat16*)p_xlo, n4x);
    int n4wa = (QKV_DIM * C_) / 4;
    split_bf16_kernel<<<(n4wa + 255) / 256, 256>>>(w_attn, (__nv_bfloat16*)p_wahi, (__nv_bfloat16*)p_walo, n4wa);
    int n4wp = (C_ * C_) / 4;
    split_bf16_kernel<<<(n4wp + 255) / 256, 256>>>(w_proj, (__nv_bfloat16*)p_wphi, (__nv_bfloat16*)p_wplo, n4wp);

    // QKV GEMM (tensor cores via mma.sync)
    dim3 g1(QKV_DIM / 128, (B_ * T_) / 128);
    gemm_mma_kernel<<<g1, 256>>>(
        (const __nv_bfloat16*)p_xhi, (const __nv_bfloat16*)p_xlo,
        (const __nv_bfloat16*)p_wahi, (const __nv_bfloat16*)p_walo,
        (float*)p_qkv, B_ * T_, QKV_DIM, C_);

    rope_rms_kernel<<<B_ * T_, 256>>>(cosb, sinb);

    dim3 ga(T_ / BQ, NH, B_);
    attn_kernel<<<ga, 256, ATTN_SMEM>>>();

    // split attention output
    int n4y = (B_ * T_ * C_) / 4;
    split_bf16_kernel<<<(n4y + 255) / 256, 256>>>((const float*)p_y, (__nv_bfloat16*)p_yhi, (__nv_bfloat16*)p_ylo, n4y);

    // out projection GEMM
    dim3 g2(C_ / 128, (B_ * T_) / 128);
    gemm_mma_kernel<<<g2, 256>>>(
        (const __nv_bfloat16*)p_yhi, (const __nv_bfloat16*)p_ylo,
        (const __nv_bfloat16*)p_wphi, (const __nv_bfloat16*)p_wplo,
        out, B_ * T_, C_, C_);
}

// round 5
// speedup vs baseline: 3.1233x; 1.6845x over previous
#include <cuda_runtime.h>
#include <cuda_bf16.h>
#include <cstdint>
#include <math.h>

// Problem constants
#define B_   2
#define T_   2048
#define C_   2048
#define NH   16
#define NKV  8
#define HD   128
#define KVD  (NKV*HD)          // 1024
#define QKV_DIM (C_ + 2*KVD)   // 4096
#define EPS_ 1.1920929e-07f
#define SCALE_ 0.08838834764831845f   // 1/sqrt(128)

// ---------------- scratch (static device globals; allocation-free) ----------
__device__ float g_qkv[(size_t)B_*T_*QKV_DIM];   // 64 MB
// bf16 hi/lo planes
__device__ __nv_bfloat16 g_xhi[(size_t)B_*T_*C_];
__device__ __nv_bfloat16 g_xlo[(size_t)B_*T_*C_];
__device__ __nv_bfloat16 g_wahi[(size_t)QKV_DIM*C_];
__device__ __nv_bfloat16 g_walo[(size_t)QKV_DIM*C_];
__device__ __nv_bfloat16 g_wphi[(size_t)C_*C_];
__device__ __nv_bfloat16 g_wplo[(size_t)C_*C_];
__device__ __nv_bfloat16 g_yhi[(size_t)B_*T_*C_];
__device__ __nv_bfloat16 g_ylo[(size_t)B_*T_*C_];
// q/k/v hi/lo planes, layouts q:[b,h,t,d] k,v:[b,kvh,t,d]
__device__ __nv_bfloat16 g_qhi[(size_t)B_*NH*T_*HD];
__device__ __nv_bfloat16 g_qlo[(size_t)B_*NH*T_*HD];
__device__ __nv_bfloat16 g_khi[(size_t)B_*NKV*T_*HD];
__device__ __nv_bfloat16 g_klo[(size_t)B_*NKV*T_*HD];
__device__ __nv_bfloat16 g_vhi[(size_t)B_*NKV*T_*HD];
__device__ __nv_bfloat16 g_vlo[(size_t)B_*NKV*T_*HD];

// ---------------------------------------------------------------------------
// helpers
// ---------------------------------------------------------------------------
__device__ __forceinline__ uint32_t smem_u32(const void* p) {
    uint32_t a;
    asm("{ .reg .u64 t; cvta.to.shared.u64 t, %1; cvt.u32.u64 %0, t; }" : "=r"(a) : "l"(p));
    return a;
}
__device__ __forceinline__ void cp_async16(uint32_t dst, const void* src) {
    asm volatile("cp.async.cg.shared.global [%0], [%1], 16;" :: "r"(dst), "l"(src));
}
__device__ __forceinline__ void cp_commit() { asm volatile("cp.async.commit_group;"); }
__device__ __forceinline__ void cp_wait1() { asm volatile("cp.async.wait_group 1;"); }
__device__ __forceinline__ void cp_wait0() { asm volatile("cp.async.wait_group 0;"); }
__device__ __forceinline__ void ldm_x4(uint32_t& r0, uint32_t& r1, uint32_t& r2, uint32_t& r3, uint32_t a) {
    asm volatile("ldmatrix.sync.aligned.m8n8.x4.shared.b16 {%0,%1,%2,%3}, [%4];"
                 : "=r"(r0), "=r"(r1), "=r"(r2), "=r"(r3) : "r"(a));
}
__device__ __forceinline__ void ldmt_x4(uint32_t& r0, uint32_t& r1, uint32_t& r2, uint32_t& r3, uint32_t a) {
    asm volatile("ldmatrix.sync.aligned.m8n8.x4.trans.shared.b16 {%0,%1,%2,%3}, [%4];"
                 : "=r"(r0), "=r"(r1), "=r"(r2), "=r"(r3) : "r"(a));
}
__device__ __forceinline__ void mma_bf16(float* d, const uint32_t* a, const uint32_t* b) {
    asm volatile(
        "mma.sync.aligned.m16n8k16.row.col.f32.bf16.bf16.f32 "
        "{%0,%1,%2,%3}, {%4,%5,%6,%7}, {%8,%9}, {%0,%1,%2,%3};"
        : "+f"(d[0]), "+f"(d[1]), "+f"(d[2]), "+f"(d[3])
        : "r"(a[0]), "r"(a[1]), "r"(a[2]), "r"(a[3]), "r"(b[0]), "r"(b[1]));
}
// pack two floats -> bf16x2 (a in low half, b in high half)
__device__ __forceinline__ uint32_t packbf(float a, float b) {
    uint32_t r;
    asm("cvt.rn.bf16x2.f32 %0, %1, %2;" : "=r"(r) : "f"(b), "f"(a));
    return r;
}
// gemm smem swizzle (64B rows, 4 chunks of 16B)
__device__ __forceinline__ uint32_t swz(int r, int c) {
    return (uint32_t)(r * 64 + ((c ^ ((r >> 1) & 3)) << 4));
}
// attention smem swizzle (256B rows, 16 chunks of 16B): xor low-3 chunk bits with row
__device__ __forceinline__ uint32_t aswz(int r, int c) {
    return (uint32_t)(r * 256 + (((c ^ r) & 7) | (c & 8)) * 16);
}

// ---------------------------------------------------------------------------
// split fp32 -> (hi, lo) bf16 planes
// ---------------------------------------------------------------------------
__global__ __launch_bounds__(256) void split_bf16_kernel(
    const float* __restrict__ in, __nv_bfloat16* __restrict__ hi,
    __nv_bfloat16* __restrict__ lo, int n4)
{
    int i = blockIdx.x * blockDim.x + threadIdx.x;
    if (i >= n4) return;
    float4 v = ((const float4*)in)[i];
    __nv_bfloat16 h0 = __float2bfloat16(v.x);
    __nv_bfloat16 h1 = __float2bfloat16(v.y);
    __nv_bfloat16 h2 = __float2bfloat16(v.z);
    __nv_bfloat16 h3 = __float2bfloat16(v.w);
    __nv_bfloat16 l0 = __float2bfloat16(v.x - __bfloat162float(h0));
    __nv_bfloat16 l1 = __float2bfloat16(v.y - __bfloat162float(h1));
    __nv_bfloat16 l2 = __float2bfloat16(v.z - __bfloat162float(h2));
    __nv_bfloat16 l3 = __float2bfloat16(v.w - __bfloat162float(h3));
    __nv_bfloat162 ha, hb, la, lb;
    ha.x = h0; ha.y = h1; hb.x = h2; hb.y = h3;
    la.x = l0; la.y = l1; lb.x = l2; lb.y = l3;
    ((__nv_bfloat162*)hi)[2 * i]     = ha;
    ((__nv_bfloat162*)hi)[2 * i + 1] = hb;
    ((__nv_bfloat162*)lo)[2 * i]     = la;
    ((__nv_bfloat162*)lo)[2 * i + 1] = lb;
}

// ---------------------------------------------------------------------------
// bf16 split GEMM (NT) via mma.sync (unchanged from R4 — passed)
// ---------------------------------------------------------------------------
__global__ __launch_bounds__(256, 2) void gemm_mma_kernel(
    const __nv_bfloat16* __restrict__ Ahi, const __nv_bfloat16* __restrict__ Alo,
    const __nv_bfloat16* __restrict__ Bhi, const __nv_bfloat16* __restrict__ Blo,
    float* __restrict__ C, int M, int N, int K)
{
    __shared__ __align__(128) unsigned char smem_raw[4 * 8192];
    uint32_t sb = smem_u32(smem_raw);

    int tid = threadIdx.x;
    int wid = tid >> 5, lane = tid & 31;
    int wm = wid >> 2, wn = wid & 3;
    int m0 = blockIdx.y * 128, n0 = blockIdx.x * 128;
    int grp = lane >> 2, qid = lane & 3;

    float acc[4][4][4];
#pragma unroll
    for (int mi = 0; mi < 4; mi++)
#pragma unroll
        for (int ni = 0; ni < 4; ni++)
#pragma unroll
            for (int r = 0; r < 4; r++) acc[mi][ni][r] = 0.f;

    int kcpp = K >> 5;
    int nch = 3 * kcpp;

    int r0_ = tid >> 2, c0_ = tid & 3;
    int r1_ = (tid + 256) >> 2, c1_ = tid & 3;

    auto issue = [&](int c) {
        int pass = c / kcpp, kc = c - pass * kcpp;
        const __nv_bfloat16* Ap = (pass == 2) ? Alo : Ahi;
        const __nv_bfloat16* Bp = (pass == 1) ? Blo : Bhi;
        int kofs = kc << 5;
        int s = c & 1;
        uint32_t aB = sb + s * 8192;
        uint32_t bB = sb + 16384 + s * 8192;
        cp_async16(aB + swz(r0_, c0_), Ap + (size_t)(m0 + r0_) * K + kofs + c0_ * 8);
        cp_async16(aB + swz(r1_, c1_), Ap + (size_t)(m0 + r1_) * K + kofs + c1_ * 8);
        cp_async16(bB + swz(r0_, c0_), Bp + (size_t)(n0 + r0_) * K + kofs + c0_ * 8);
        cp_async16(bB + swz(r1_, c1_), Bp + (size_t)(n0 + r1_) * K + kofs + c1_ * 8);
        cp_commit();
    };

    issue(0);

    int lrow_add = (lane & 7) + (((lane >> 3) & 1) << 3);
    int lchunk_add = lane >> 4;

    for (int c = 0; c < nch; c++) {
        bool have_next = (c + 1 < nch);
        if (have_next) issue(c + 1);
        if (have_next) cp_wait1(); else cp_wait0();
        __syncthreads();

        int s = c & 1;
        uint32_t aB = sb + s * 8192;
        uint32_t bB = sb + 16384 + s * 8192;

#pragma unroll
        for (int ks = 0; ks < 2; ks++) {
            int cbase = ks * 2 + lchunk_add;
            uint32_t af[4][4];
#pragma unroll
            for (int mi = 0; mi < 4; mi++) {
                int row = wm * 64 + mi * 16 + lrow_add;
                ldm_x4(af[mi][0], af[mi][1], af[mi][2], af[mi][3], aB + swz(row, cbase));
            }
            uint32_t bf[4][2];
#pragma unroll
            for (int p = 0; p < 2; p++) {
                int row = wn * 32 + p * 16 + lrow_add;
                uint32_t t0, t1, t2, t3;
                ldm_x4(t0, t1, t2, t3, bB + swz(row, cbase));
                bf[p * 2][0] = t0;     bf[p * 2][1] = t2;
                bf[p * 2 + 1][0] = t1; bf[p * 2 + 1][1] = t3;
            }
#pragma unroll
            for (int mi = 0; mi < 4; mi++)
#pragma unroll
                for (int ni = 0; ni < 4; ni++)
                    mma_bf16(acc[mi][ni], af[mi], bf[ni]);
        }
        __syncthreads();
    }

#pragma unroll
    for (int mi = 0; mi < 4; mi++) {
        int rbase = m0 + wm * 64 + mi * 16 + grp;
#pragma unroll
        for (int ni = 0; ni < 4; ni++) {
            int col = n0 + wn * 32 + ni * 8 + qid * 2;
            float* p0 = C + (size_t)rbase * N + col;
            float* p1 = C + (size_t)(rbase + 8) * N + col;
            p0[0] = acc[mi][ni][0]; p0[1] = acc[mi][ni][1];
            p1[0] = acc[mi][ni][2]; p1[1] = acc[mi][ni][3];
        }
    }
}

// ---------------------------------------------------------------------------
// RoPE + RMSnorm + split to bf16 hi/lo planes (q pre-scaled by 1/sqrt(d))
// ---------------------------------------------------------------------------
__global__ __launch_bounds__(256) void rope_rms_kernel(
    const float* __restrict__ cosb, const float* __restrict__ sinb)
{
    int bt = blockIdx.x;
    int b = bt / T_, t = bt % T_;
    int warp = threadIdx.x >> 5, lane = threadIdx.x & 31;
    const float* base = g_qkv + (size_t)bt * QKV_DIM;

    float c0 = cosb[t * 64 + lane], c1 = cosb[t * 64 + lane + 32];
    float s0 = sinb[t * 64 + lane], s1 = sinb[t * 64 + lane + 32];

    for (int hh = warp; hh < NH + NKV; hh += 8) {
        const float* src;
        __nv_bfloat16 *dhi, *dlo;
        float scl;
        if (hh < NH) {
            src = base + hh * HD;
            size_t o = ((size_t)(b * NH + hh) * T_ + t) * HD;
            dhi = g_qhi + o; dlo = g_qlo + o; scl = SCALE_;
        } else {
            int kv = hh - NH;
            src = base + C_ + kv * HD;
            size_t o = ((size_t)(b * NKV + kv) * T_ + t) * HD;
            dhi = g_khi + o; dlo = g_klo + o; scl = 1.0f;
        }
        float v0 = src[lane], v1 = src[lane + 32], v2 = src[lane + 64], v3 = src[lane + 96];
        float y0 =  v0 * c0 + v2 * s0;
        float y2 = -v0 * s0 + v2 * c0;
        float y1 =  v1 * c1 + v3 * s1;
        float y3 = -v1 * s1 + v3 * c1;
        float ss = y0 * y0 + y1 * y1 + y2 * y2 + y3 * y3;
#pragma unroll
        for (int o = 16; o > 0; o >>= 1) ss += __shfl_xor_sync(0xffffffffu, ss, o);
        float r = rsqrtf(ss * (1.0f / HD) + EPS_) * scl;
        float w0 = y0 * r, w1 = y1 * r, w2 = y2 * r, w3 = y3 * r;
        __nv_bfloat16 h0 = __float2bfloat16(w0), h1 = __float2bfloat16(w1);
        __nv_bfloat16 h2 = __float2bfloat16(w2), h3 = __float2bfloat16(w3);
        dhi[lane]      = h0; dlo[lane]      = __float2bfloat16(w0 - __bfloat162float(h0));
        dhi[lane + 32] = h1; dlo[lane + 32] = __float2bfloat16(w1 - __bfloat162float(h1));
        dhi[lane + 64] = h2; dlo[lane + 64] = __float2bfloat16(w2 - __bfloat162float(h2));
        dhi[lane + 96] = h3; dlo[lane + 96] = __float2bfloat16(w3 - __bfloat162float(h3));
    }
    // V split (8 kv heads, one per warp); lane covers d = 4*lane..4*lane+3
    {
        int kv = warp;
        const float4* src = (const float4*)(base + C_ + KVD + kv * HD);
        float4 v = src[lane];
        size_t o = ((size_t)(b * NKV + kv) * T_ + t) * HD + 4 * lane;
        __nv_bfloat16 h0 = __float2bfloat16(v.x), h1 = __float2bfloat16(v.y);
        __nv_bfloat16 h2 = __float2bfloat16(v.z), h3 = __float2bfloat16(v.w);
        __nv_bfloat162 hа, hb, la, lb;
        hа.x = h0; hа.y = h1; hb.x = h2; hb.y = h3;
        la.x = __float2bfloat16(v.x - __bfloat162float(h0));
        la.y = __float2bfloat16(v.y - __bfloat162float(h1));
        lb.x = __float2bfloat16(v.z - __bfloat162float(h2));
        lb.y = __float2bfloat16(v.w - __bfloat162float(h3));
        *(__nv_bfloat162*)(g_vhi + o)     = hа;
        *(__nv_bfloat162*)(g_vhi + o + 2) = hb;
        *(__nv_bfloat162*)(g_vlo + o)     = la;
        *(__nv_bfloat162*)(g_vlo + o + 2) = lb;
    }
}

// ---------------------------------------------------------------------------
// Tensor-core flash attention, causal, GQA, bf16 hi/lo 3-pass.
// Block: 128 threads = 4 warps, BQ=64 (warp strip 16 q-rows), BK=64.
// Writes yhi/ylo planes directly.
// ---------------------------------------------------------------------------
#define ATT_SMEM (6 * 16384)   // QH,QL,KH,KL,VH,VL tiles of 64x128 bf16

__global__ __launch_bounds__(128) void attn_mma_kernel()
{
    extern __shared__ unsigned char attn_smem_raw[];
    uint32_t sb = smem_u32(attn_smem_raw);
    const uint32_t QH = 0, QL = 16384, KHs = 32768, KLs = 49152, VHs = 65536, VLs = 81920;

    int qt = blockIdx.x, h = blockIdx.y, b = blockIdx.z;
    int kvh = h >> 1;
    int tid = threadIdx.x, wid = tid >> 5, lane = tid & 31;
    int grp = lane >> 2, qid = lane & 3;
    int q0 = qt * 64;

    const __nv_bfloat16* qh = g_qhi + ((size_t)(b * NH + h) * T_ + q0) * HD;
    const __nv_bfloat16* ql = g_qlo + ((size_t)(b * NH + h) * T_ + q0) * HD;
    const __nv_bfloat16* kh = g_khi + ((size_t)(b * NKV + kvh) * T_) * HD;
    const __nv_bfloat16* kl = g_klo + ((size_t)(b * NKV + kvh) * T_) * HD;
    const __nv_bfloat16* vh = g_vhi + ((size_t)(b * NKV + kvh) * T_) * HD;
    const __nv_bfloat16* vl = g_vlo + ((size_t)(b * NKV + kvh) * T_) * HD;

    // load Q hi/lo
    for (int i = tid; i < 1024; i += 128) {
        int r = i >> 4, c = i & 15;
        uint32_t o = aswz(r, c);
        cp_async16(sb + QH + o, qh + (size_t)r * HD + c * 8);
        cp_async16(sb + QL + o, ql + (size_t)r * HD + c * 8);
    }
    cp_commit();

    float O[16][4];
#pragma unroll
    for (int t = 0; t < 16; t++)
#pragma unroll
        for (int r = 0; r < 4; r++) O[t][r] = 0.f;
    float m0 = -1e30f, m1 = -1e30f, l0 = 0.f, l1 = 0.f;

    int csel = lane >> 4;
    int arow = wid * 16 + (lane & 15);

    for (int kt = 0; kt <= qt; kt++) {
        int k0 = kt * 64;
        for (int i = tid; i < 1024; i += 128) {
            int r = i >> 4, c = i & 15;
            size_t g = (size_t)(k0 + r) * HD + c * 8;
            uint32_t o = aswz(r, c);
            cp_async16(sb + KHs + o, kh + g);
            cp_async16(sb + KLs + o, kl + g);
            cp_async16(sb + VHs + o, vh + g);
            cp_async16(sb + VLs + o, vl + g);
        }
        cp_commit();
        cp_wait0();
        __syncthreads();

        // S = Q K^T (3-pass hi/lo), warp strip 16 x 64, tiles s[0..7]
        float s[8][4];
#pragma unroll
        for (int j = 0; j < 8; j++)
#pragma unroll
            for (int r = 0; r < 4; r++) s[j][r] = 0.f;

#pragma unroll
        for (int ks = 0; ks < 8; ks++) {
            int ch = 2 * ks + csel;
            uint32_t ah[4], al[4];
            ldm_x4(ah[0], ah[1], ah[2], ah[3], sb + QH + aswz(arow, ch));
            ldm_x4(al[0], al[1], al[2], al[3], sb + QL + aswz(arow, ch));
#pragma unroll
            for (int nt = 0; nt < 4; nt++) {
                int krow = nt * 16 + (lane & 15);
                uint32_t t0, t1, t2, t3, u0, u1, u2, u3;
                ldm_x4(t0, t1, t2, t3, sb + KHs + aswz(krow, ch));
                ldm_x4(u0, u1, u2, u3, sb + KLs + aswz(krow, ch));
                uint32_t bh0[2] = {t0, t2}, bh1[2] = {t1, t3};
                uint32_t bl0[2] = {u0, u2}, bl1[2] = {u1, u3};
                mma_bf16(s[2 * nt], ah, bh0);     mma_bf16(s[2 * nt + 1], ah, bh1);
                mma_bf16(s[2 * nt], al, bh0);     mma_bf16(s[2 * nt + 1], al, bh1);
                mma_bf16(s[2 * nt], ah, bl0);     mma_bf16(s[2 * nt + 1], ah, bl1);
            }
        }

        // causal mask (diagonal tile only)
        if (kt == qt) {
            int r0g = q0 + wid * 16 + grp;
#pragma unroll
            for (int j = 0; j < 8; j++) {
                int cb = k0 + j * 8 + 2 * qid;
                if (cb > r0g)         s[j][0] = -1e30f;
                if (cb + 1 > r0g)     s[j][1] = -1e30f;
                if (cb > r0g + 8)     s[j][2] = -1e30f;
                if (cb + 1 > r0g + 8) s[j][3] = -1e30f;
            }
        }

        // online softmax (rows grp, grp+8; quad lanes share a row)
        float mx0 = -1e30f, mx1 = -1e30f;
#pragma unroll
        for (int j = 0; j < 8; j++) {
            mx0 = fmaxf(mx0, fmaxf(s[j][0], s[j][1]));
            mx1 = fmaxf(mx1, fmaxf(s[j][2], s[j][3]));
        }
        mx0 = fmaxf(mx0, __shfl_xor_sync(0xffffffffu, mx0, 1));
        mx0 = fmaxf(mx0, __shfl_xor_sync(0xffffffffu, mx0, 2));
        mx1 = fmaxf(mx1, __shfl_xor_sync(0xffffffffu, mx1, 1));
        mx1 = fmaxf(mx1, __shfl_xor_sync(0xffffffffu, mx1, 2));
        float nm0 = fmaxf(m0, mx0), nm1 = fmaxf(m1, mx1);
        float f0 = __expf(m0 - nm0), f1 = __expf(m1 - nm1);
        m0 = nm0; m1 = nm1;
        float sum0 = 0.f, sum1 = 0.f;
#pragma unroll
        for (int j = 0; j < 8; j++) {
            s[j][0] = __expf(s[j][0] - nm0);
            s[j][1] = __expf(s[j][1] - nm0);
            s[j][2] = __expf(s[j][2] - nm1);
            s[j][3] = __expf(s[j][3] - nm1);
            sum0 += s[j][0] + s[j][1];
            sum1 += s[j][2] + s[j][3];
        }
        sum0 += __shfl_xor_sync(0xffffffffu, sum0, 1);
        sum0 += __shfl_xor_sync(0xffffffffu, sum0, 2);
        sum1 += __shfl_xor_sync(0xffffffffu, sum1, 1);
        sum1 += __shfl_xor_sync(0xffffffffu, sum1, 2);
        l0 = l0 * f0 + sum0;
        l1 = l1 * f1 + sum1;
#pragma unroll
        for (int t = 0; t < 16; t++) {
            O[t][0] *= f0; O[t][1] *= f0; O[t][2] *= f1; O[t][3] *= f1;
        }

        // O += P V (3-pass: Phi*Vhi + Plo*Vhi + Phi*Vlo)
#pragma unroll
        for (int kc = 0; kc < 4; kc++) {
            float p00 = s[2 * kc][0], p01 = s[2 * kc][1], p02 = s[2 * kc][2], p03 = s[2 * kc][3];
            float p10 = s[2 * kc + 1][0], p11 = s[2 * kc + 1][1], p12 = s[2 * kc + 1][2], p13 = s[2 * kc + 1][3];
            uint32_t ph[4], pl[4];
            ph[0] = packbf(p00, p01); ph[1] = packbf(p02, p03);
            ph[2] = packbf(p10, p11); ph[3] = packbf(p12, p13);
            float q00 = p00 - __bfloat162float(__float2bfloat16(p00));
            float q01 = p01 - __bfloat162float(__float2bfloat16(p01));
            float q02 = p02 - __bfloat162float(__float2bfloat16(p02));
            float q03 = p03 - __bfloat162float(__float2bfloat16(p03));
            float q10 = p10 - __bfloat162float(__float2bfloat16(p10));
            float q11 = p11 - __bfloat162float(__float2bfloat16(p11));
            float q12 = p12 - __bfloat162float(__float2bfloat16(p12));
            float q13 = p13 - __bfloat162float(__float2bfloat16(p13));
            pl[0] = packbf(q00, q01); pl[1] = packbf(q02, q03);
            pl[2] = packbf(q10, q11); pl[3] = packbf(q12, q13);

            int vrow = kc * 16 + ((lane >> 3) & 1) * 8 + (lane & 7);
#pragma unroll
            for (int dn = 0; dn < 8; dn++) {
                int ch2 = 2 * dn + csel;
                uint32_t t0, t1, t2, t3, u0, u1, u2, u3;
                ldmt_x4(t0, t1, t2, t3, sb + VHs + aswz(vrow, ch2));
                ldmt_x4(u0, u1, u2, u3, sb + VLs + aswz(vrow, ch2));
                uint32_t bh0[2] = {t0, t1}, bh1[2] = {t2, t3};
                uint32_t bl0[2] = {u0, u1}, bl1[2] = {u2, u3};
                mma_bf16(O[2 * dn], ph, bh0);     mma_bf16(O[2 * dn + 1], ph, bh1);
                mma_bf16(O[2 * dn], pl, bh0);     mma_bf16(O[2 * dn + 1], pl, bh1);
                mma_bf16(O[2 * dn], ph, bl0);     mma_bf16(O[2 * dn + 1], ph, bl1);
            }
        }
        __syncthreads();
    }

    // epilogue: normalize, split to yhi/ylo bf16 planes
    float i0 = 1.0f / l0, i1 = 1.0f / l1;
    int r0g = q0 + wid * 16 + grp;
    size_t base0 = ((size_t)(b * T_) + r0g) * C_ + h * HD;
    size_t base1 = base0 + (size_t)8 * C_;
#pragma unroll
    for (int t = 0; t < 16; t++) {
        int col = t * 8 + 2 * qid;
        float v0 = O[t][0] * i0, v1 = O[t][1] * i0;
        float v2 = O[t][2] * i1, v3 = O[t][3] * i1;
        float h0 = __bfloat162float(__float2bfloat16(v0));
        float h1 = __bfloat162float(__float2bfloat16(v1));
        float h2 = __bfloat162float(__float2bfloat16(v2));
        float h3 = __bfloat162float(__float2bfloat16(v3));
        *(uint32_t*)(g_yhi + base0 + col) = packbf(v0, v1);
        *(uint32_t*)(g_ylo + base0 + col) = packbf(v0 - h0, v1 - h1);
        *(uint32_t*)(g_yhi + base1 + col) = packbf(v2, v3);
        *(uint32_t*)(g_ylo + base1 + col) = packbf(v2 - h2, v3 - h3);
    }
}

// ---------------------------------------------------------------------------
// Launch pipeline
// ---------------------------------------------------------------------------
extern "C" void kernel_launch(void* const* d_in, const int* in_sizes, int n_in,
                              void* d_out, int out_size)
{
    const float* x      = (const float*)d_in[0];
    const float* w_attn = (const float*)d_in[1];
    const float* w_proj = (const float*)d_in[2];
    const float* cosb   = (const float*)d_in[3];
    const float* sinb   = (const float*)d_in[4];
    float* out = (float*)d_out;

    void *p_qkv, *p_xhi, *p_xlo, *p_wahi, *p_walo, *p_wphi, *p_wplo, *p_yhi, *p_ylo;
    cudaGetSymbolAddress(&p_qkv, g_qkv);
    cudaGetSymbolAddress(&p_xhi, g_xhi);  cudaGetSymbolAddress(&p_xlo, g_xlo);
    cudaGetSymbolAddress(&p_wahi, g_wahi); cudaGetSymbolAddress(&p_walo, g_walo);
    cudaGetSymbolAddress(&p_wphi, g_wphi); cudaGetSymbolAddress(&p_wplo, g_wplo);
    cudaGetSymbolAddress(&p_yhi, g_yhi);  cudaGetSymbolAddress(&p_ylo, g_ylo);

    cudaFuncSetAttribute(attn_mma_kernel, cudaFuncAttributeMaxDynamicSharedMemorySize, ATT_SMEM);

    // split inputs into bf16 hi/lo planes
    int n4x = (B_ * T_ * C_) / 4;
    split_bf16_kernel<<<(n4x + 255) / 256, 256>>>(x, (__nv_bfloat16*)p_xhi, (__nv_bfloat16*)p_xlo, n4x);
    int n4wa = (QKV_DIM * C_) / 4;
    split_bf16_kernel<<<(n4wa + 255) / 256, 256>>>(w_attn, (__nv_bfloat16*)p_wahi, (__nv_bfloat16*)p_walo, n4wa);
    int n4wp = (C_ * C_) / 4;
    split_bf16_kernel<<<(n4wp + 255) / 256, 256>>>(w_proj, (__nv_bfloat16*)p_wphi, (__nv_bfloat16*)p_wplo, n4wp);

    // QKV GEMM (tensor cores via mma.sync)
    dim3 g1(QKV_DIM / 128, (B_ * T_) / 128);
    gemm_mma_kernel<<<g1, 256>>>(
        (const __nv_bfloat16*)p_xhi, (const __nv_bfloat16*)p_xlo,
        (const __nv_bfloat16*)p_wahi, (const __nv_bfloat16*)p_walo,
        (float*)p_qkv, B_ * T_, QKV_DIM, C_);

    // RoPE + RMSnorm + hi/lo split
    rope_rms_kernel<<<B_ * T_, 256>>>(cosb, sinb);

    // tensor-core flash attention (writes yhi/ylo)
    dim3 ga(T_ / 64, NH, B_);
    attn_mma_kernel<<<ga, 128, ATT_SMEM>>>();

    // out projection GEMM
    dim3 g2(C_ / 128, (B_ * T_) / 128);
    gemm_mma_kernel<<<g2, 256>>>(
        (const __nv_bfloat16*)p_yhi, (const __nv_bfloat16*)p_ylo,
        (const __nv_bfloat16*)p_wphi, (const __nv_bfloat16*)p_wplo,
        out, B_ * T_, C_, C_);
}

// round 6
// speedup vs baseline: 3.2632x; 1.0448x over previous
#include <cuda_runtime.h>
#include <cuda_bf16.h>
#include <cstdint>
#include <math.h>

// Problem constants
#define B_   2
#define T_   2048
#define C_   2048
#define NH   16
#define NKV  8
#define HD   128
#define KVD  (NKV*HD)          // 1024
#define QKV_DIM (C_ + 2*KVD)   // 4096
#define EPS_ 1.1920929e-07f
#define SCALE_ 0.08838834764831845f   // 1/sqrt(128)

// ---------------- scratch (static device globals; allocation-free) ----------
__device__ float g_qkv[(size_t)B_*T_*QKV_DIM];   // 64 MB
// bf16 hi/lo planes
__device__ __nv_bfloat16 g_xhi[(size_t)B_*T_*C_];
__device__ __nv_bfloat16 g_xlo[(size_t)B_*T_*C_];
__device__ __nv_bfloat16 g_wahi[(size_t)QKV_DIM*C_];
__device__ __nv_bfloat16 g_walo[(size_t)QKV_DIM*C_];
__device__ __nv_bfloat16 g_wphi[(size_t)C_*C_];
__device__ __nv_bfloat16 g_wplo[(size_t)C_*C_];
__device__ __nv_bfloat16 g_yhi[(size_t)B_*T_*C_];
__device__ __nv_bfloat16 g_ylo[(size_t)B_*T_*C_];
// q/k/v hi/lo planes, layouts q:[b,h,t,d] k,v:[b,kvh,t,d]
__device__ __nv_bfloat16 g_qhi[(size_t)B_*NH*T_*HD];
__device__ __nv_bfloat16 g_qlo[(size_t)B_*NH*T_*HD];
__device__ __nv_bfloat16 g_khi[(size_t)B_*NKV*T_*HD];
__device__ __nv_bfloat16 g_klo[(size_t)B_*NKV*T_*HD];
__device__ __nv_bfloat16 g_vhi[(size_t)B_*NKV*T_*HD];
__device__ __nv_bfloat16 g_vlo[(size_t)B_*NKV*T_*HD];

// ---------------------------------------------------------------------------
// helpers
// ---------------------------------------------------------------------------
__device__ __forceinline__ uint32_t smem_u32(const void* p) {
    uint32_t a;
    asm("{ .reg .u64 t; cvta.to.shared.u64 t, %1; cvt.u32.u64 %0, t; }" : "=r"(a) : "l"(p));
    return a;
}
__device__ __forceinline__ void cp_async16(uint32_t dst, const void* src) {
    asm volatile("cp.async.cg.shared.global [%0], [%1], 16;" :: "r"(dst), "l"(src));
}
__device__ __forceinline__ void cp_commit() { asm volatile("cp.async.commit_group;"); }
__device__ __forceinline__ void cp_wait1() { asm volatile("cp.async.wait_group 1;"); }
__device__ __forceinline__ void cp_wait0() { asm volatile("cp.async.wait_group 0;"); }
__device__ __forceinline__ void ldm_x4(uint32_t& r0, uint32_t& r1, uint32_t& r2, uint32_t& r3, uint32_t a) {
    asm volatile("ldmatrix.sync.aligned.m8n8.x4.shared.b16 {%0,%1,%2,%3}, [%4];"
                 : "=r"(r0), "=r"(r1), "=r"(r2), "=r"(r3) : "r"(a));
}
__device__ __forceinline__ void ldmt_x4(uint32_t& r0, uint32_t& r1, uint32_t& r2, uint32_t& r3, uint32_t a) {
    asm volatile("ldmatrix.sync.aligned.m8n8.x4.trans.shared.b16 {%0,%1,%2,%3}, [%4];"
                 : "=r"(r0), "=r"(r1), "=r"(r2), "=r"(r3) : "r"(a));
}
__device__ __forceinline__ void mma_bf16(float* d, const uint32_t* a, const uint32_t* b) {
    asm volatile(
        "mma.sync.aligned.m16n8k16.row.col.f32.bf16.bf16.f32 "
        "{%0,%1,%2,%3}, {%4,%5,%6,%7}, {%8,%9}, {%0,%1,%2,%3};"
        : "+f"(d[0]), "+f"(d[1]), "+f"(d[2]), "+f"(d[3])
        : "r"(a[0]), "r"(a[1]), "r"(a[2]), "r"(a[3]), "r"(b[0]), "r"(b[1]));
}
__device__ __forceinline__ uint32_t packbf(float a, float b) {
    uint32_t r;
    asm("cvt.rn.bf16x2.f32 %0, %1, %2;" : "=r"(r) : "f"(b), "f"(a));
    return r;
}
// gemm smem swizzle (64B rows, 4 chunks of 16B)
__device__ __forceinline__ uint32_t swz(int r, int c) {
    return (uint32_t)(r * 64 + ((c ^ ((r >> 1) & 3)) << 4));
}
// attention smem swizzle (256B rows, 16 chunks of 16B)
__device__ __forceinline__ uint32_t aswz(int r, int c) {
    return (uint32_t)(r * 256 + (((c ^ r) & 7) | (c & 8)) * 16);
}

// ---------------------------------------------------------------------------
// split fp32 -> (hi, lo) bf16 planes
// ---------------------------------------------------------------------------
__global__ __launch_bounds__(256) void split_bf16_kernel(
    const float* __restrict__ in, __nv_bfloat16* __restrict__ hi,
    __nv_bfloat16* __restrict__ lo, int n4)
{
    int i = blockIdx.x * blockDim.x + threadIdx.x;
    if (i >= n4) return;
    float4 v = ((const float4*)in)[i];
    __nv_bfloat16 h0 = __float2bfloat16(v.x);
    __nv_bfloat16 h1 = __float2bfloat16(v.y);
    __nv_bfloat16 h2 = __float2bfloat16(v.z);
    __nv_bfloat16 h3 = __float2bfloat16(v.w);
    __nv_bfloat16 l0 = __float2bfloat16(v.x - __bfloat162float(h0));
    __nv_bfloat16 l1 = __float2bfloat16(v.y - __bfloat162float(h1));
    __nv_bfloat16 l2 = __float2bfloat16(v.z - __bfloat162float(h2));
    __nv_bfloat16 l3 = __float2bfloat16(v.w - __bfloat162float(h3));
    __nv_bfloat162 ha, hb, la, lb;
    ha.x = h0; ha.y = h1; hb.x = h2; hb.y = h3;
    la.x = l0; la.y = l1; lb.x = l2; lb.y = l3;
    ((__nv_bfloat162*)hi)[2 * i]     = ha;
    ((__nv_bfloat162*)hi)[2 * i + 1] = hb;
    ((__nv_bfloat162*)lo)[2 * i]     = la;
    ((__nv_bfloat162*)lo)[2 * i + 1] = lb;
}

// ---------------------------------------------------------------------------
// bf16 split GEMM (NT) via mma.sync: C[m,n] = sum_k A[m,k]*B[n,k], fp32 acc.
// 3 passes: Ahi*Bhi + Ahi*Blo + Alo*Bhi (register accumulation).
// CTA tile 128x128, BK=32, 128 threads = 4 warps (2x2), warp tile 64x64.
// 3-stage cp.async pipeline, ONE barrier per chunk.
// ---------------------------------------------------------------------------
__global__ __launch_bounds__(128, 2) void gemm_mma_kernel(
    const __nv_bfloat16* __restrict__ Ahi, const __nv_bfloat16* __restrict__ Alo,
    const __nv_bfloat16* __restrict__ Bhi, const __nv_bfloat16* __restrict__ Blo,
    float* __restrict__ C, int M, int N, int K)
{
    __shared__ __align__(128) unsigned char smem_raw[3 * 16384]; // 3 stages x (8KB A + 8KB B)
    uint32_t sb = smem_u32(smem_raw);

    int tid = threadIdx.x;
    int wid = tid >> 5, lane = tid & 31;
    int wm = wid >> 1, wn = wid & 1;      // warp grid 2x2
    int m0 = blockIdx.y * 128, n0 = blockIdx.x * 128;
    int grp = lane >> 2, qid = lane & 3;

    float acc[4][8][4];
#pragma unroll
    for (int mi = 0; mi < 4; mi++)
#pragma unroll
        for (int ni = 0; ni < 8; ni++)
#pragma unroll
            for (int r = 0; r < 4; r++) acc[mi][ni][r] = 0.f;

    int kcpp = K >> 5;       // BK=32 chunks per pass
    int nch = 3 * kcpp;

    // per-thread load assignment: 4 chunks of A, 4 of B per tile (128 threads)
    auto issue = [&](int c) {
        int pass = c / kcpp, kc = c - pass * kcpp;
        const __nv_bfloat16* Ap = (pass == 2) ? Alo : Ahi;
        const __nv_bfloat16* Bp = (pass == 1) ? Blo : Bhi;
        int kofs = kc << 5;
        int s = c % 3;
        uint32_t aB = sb + s * 16384;
        uint32_t bB = aB + 8192;
#pragma unroll
        for (int it = 0; it < 4; it++) {
            int idx = tid + it * 128;           // 0..511
            int r = idx >> 2, ch = idx & 3;
            uint32_t o = swz(r, ch);
            cp_async16(aB + o, Ap + (size_t)(m0 + r) * K + kofs + ch * 8);
            cp_async16(bB + o, Bp + (size_t)(n0 + r) * K + kofs + ch * 8);
        }
        cp_commit();
    };

    issue(0);
    issue(1);

    int lrow_add = (lane & 7) + (((lane >> 3) & 1) << 3);
    int lchunk_add = lane >> 4;

    for (int c = 0; c < nch; c++) {
        if (c + 1 < nch) cp_wait1(); else cp_wait0();
        __syncthreads();
        if (c + 2 < nch) issue(c + 2);

        int s = c % 3;
        uint32_t aB = sb + s * 16384;
        uint32_t bB = aB + 8192;

#pragma unroll
        for (int ks = 0; ks < 2; ks++) {
            int cbase = ks * 2 + lchunk_add;
            uint32_t af[4][4];
#pragma unroll
            for (int mi = 0; mi < 4; mi++) {
                int row = wm * 64 + mi * 16 + lrow_add;
                ldm_x4(af[mi][0], af[mi][1], af[mi][2], af[mi][3], aB + swz(row, cbase));
            }
            uint32_t bf[8][2];
#pragma unroll
            for (int p = 0; p < 4; p++) {
                int row = wn * 64 + p * 16 + lrow_add;
                uint32_t t0, t1, t2, t3;
                ldm_x4(t0, t1, t2, t3, bB + swz(row, cbase));
                bf[p * 2][0] = t0;     bf[p * 2][1] = t2;
                bf[p * 2 + 1][0] = t1; bf[p * 2 + 1][1] = t3;
            }
#pragma unroll
            for (int mi = 0; mi < 4; mi++)
#pragma unroll
                for (int ni = 0; ni < 8; ni++)
                    mma_bf16(acc[mi][ni], af[mi], bf[ni]);
        }
    }

    // epilogue
#pragma unroll
    for (int mi = 0; mi < 4; mi++) {
        int rbase = m0 + wm * 64 + mi * 16 + grp;
#pragma unroll
        for (int ni = 0; ni < 8; ni++) {
            int col = n0 + wn * 64 + ni * 8 + qid * 2;
            float* p0 = C + (size_t)rbase * N + col;
            float* p1 = C + (size_t)(rbase + 8) * N + col;
            p0[0] = acc[mi][ni][0]; p0[1] = acc[mi][ni][1];
            p1[0] = acc[mi][ni][2]; p1[1] = acc[mi][ni][3];
        }
    }
}

// ---------------------------------------------------------------------------
// RoPE + RMSnorm + split to bf16 hi/lo planes (q pre-scaled by 1/sqrt(d))
// ---------------------------------------------------------------------------
__global__ __launch_bounds__(256) void rope_rms_kernel(
    const float* __restrict__ cosb, const float* __restrict__ sinb)
{
    int bt = blockIdx.x;
    int b = bt / T_, t = bt % T_;
    int warp = threadIdx.x >> 5, lane = threadIdx.x & 31;
    const float* base = g_qkv + (size_t)bt * QKV_DIM;

    float c0 = cosb[t * 64 + lane], c1 = cosb[t * 64 + lane + 32];
    float s0 = sinb[t * 64 + lane], s1 = sinb[t * 64 + lane + 32];

    for (int hh = warp; hh < NH + NKV; hh += 8) {
        const float* src;
        __nv_bfloat16 *dhi, *dlo;
        float scl;
        if (hh < NH) {
            src = base + hh * HD;
            size_t o = ((size_t)(b * NH + hh) * T_ + t) * HD;
            dhi = g_qhi + o; dlo = g_qlo + o; scl = SCALE_;
        } else {
            int kv = hh - NH;
            src = base + C_ + kv * HD;
            size_t o = ((size_t)(b * NKV + kv) * T_ + t) * HD;
            dhi = g_khi + o; dlo = g_klo + o; scl = 1.0f;
        }
        float v0 = src[lane], v1 = src[lane + 32], v2 = src[lane + 64], v3 = src[lane + 96];
        float y0 =  v0 * c0 + v2 * s0;
        float y2 = -v0 * s0 + v2 * c0;
        float y1 =  v1 * c1 + v3 * s1;
        float y3 = -v1 * s1 + v3 * c1;
        float ss = y0 * y0 + y1 * y1 + y2 * y2 + y3 * y3;
#pragma unroll
        for (int o = 16; o > 0; o >>= 1) ss += __shfl_xor_sync(0xffffffffu, ss, o);
        float r = rsqrtf(ss * (1.0f / HD) + EPS_) * scl;
        float w0 = y0 * r, w1 = y1 * r, w2 = y2 * r, w3 = y3 * r;
        __nv_bfloat16 h0 = __float2bfloat16(w0), h1 = __float2bfloat16(w1);
        __nv_bfloat16 h2 = __float2bfloat16(w2), h3 = __float2bfloat16(w3);
        dhi[lane]      = h0; dlo[lane]      = __float2bfloat16(w0 - __bfloat162float(h0));
        dhi[lane + 32] = h1; dlo[lane + 32] = __float2bfloat16(w1 - __bfloat162float(h1));
        dhi[lane + 64] = h2; dlo[lane + 64] = __float2bfloat16(w2 - __bfloat162float(h2));
        dhi[lane + 96] = h3; dlo[lane + 96] = __float2bfloat16(w3 - __bfloat162float(h3));
    }
    // V split
    {
        int kv = warp;
        const float4* src = (const float4*)(base + C_ + KVD + kv * HD);
        float4 v = src[lane];
        size_t o = ((size_t)(b * NKV + kv) * T_ + t) * HD + 4 * lane;
        __nv_bfloat16 h0 = __float2bfloat16(v.x), h1 = __float2bfloat16(v.y);
        __nv_bfloat16 h2 = __float2bfloat16(v.z), h3 = __float2bfloat16(v.w);
        __nv_bfloat162 ha, hb, la, lb;
        ha.x = h0; ha.y = h1; hb.x = h2; hb.y = h3;
        la.x = __float2bfloat16(v.x - __bfloat162float(h0));
        la.y = __float2bfloat16(v.y - __bfloat162float(h1));
        lb.x = __float2bfloat16(v.z - __bfloat162float(h2));
        lb.y = __float2bfloat16(v.w - __bfloat162float(h3));
        *(__nv_bfloat162*)(g_vhi + o)     = ha;
        *(__nv_bfloat162*)(g_vhi + o + 2) = hb;
        *(__nv_bfloat162*)(g_vlo + o)     = la;
        *(__nv_bfloat162*)(g_vlo + o + 2) = lb;
    }
}

// ---------------------------------------------------------------------------
// Tensor-core flash attention, causal, GQA, bf16 hi/lo 3-pass (unchanged — passed)
// ---------------------------------------------------------------------------
#define ATT_SMEM (6 * 16384)

__global__ __launch_bounds__(128) void attn_mma_kernel()
{
    extern __shared__ unsigned char attn_smem_raw[];
    uint32_t sb = smem_u32(attn_smem_raw);
    const uint32_t QH = 0, QL = 16384, KHs = 32768, KLs = 49152, VHs = 65536, VLs = 81920;

    int qt = blockIdx.x, h = blockIdx.y, b = blockIdx.z;
    int kvh = h >> 1;
    int tid = threadIdx.x, wid = tid >> 5, lane = tid & 31;
    int grp = lane >> 2, qid = lane & 3;
    int q0 = qt * 64;

    const __nv_bfloat16* qh = g_qhi + ((size_t)(b * NH + h) * T_ + q0) * HD;
    const __nv_bfloat16* ql = g_qlo + ((size_t)(b * NH + h) * T_ + q0) * HD;
    const __nv_bfloat16* kh = g_khi + ((size_t)(b * NKV + kvh) * T_) * HD;
    const __nv_bfloat16* kl = g_klo + ((size_t)(b * NKV + kvh) * T_) * HD;
    const __nv_bfloat16* vh = g_vhi + ((size_t)(b * NKV + kvh) * T_) * HD;
    const __nv_bfloat16* vl = g_vlo + ((size_t)(b * NKV + kvh) * T_) * HD;

    for (int i = tid; i < 1024; i += 128) {
        int r = i >> 4, c = i & 15;
        uint32_t o = aswz(r, c);
        cp_async16(sb + QH + o, qh + (size_t)r * HD + c * 8);
        cp_async16(sb + QL + o, ql + (size_t)r * HD + c * 8);
    }
    cp_commit();

    float O[16][4];
#pragma unroll
    for (int t = 0; t < 16; t++)
#pragma unroll
        for (int r = 0; r < 4; r++) O[t][r] = 0.f;
    float m0 = -1e30f, m1 = -1e30f, l0 = 0.f, l1 = 0.f;

    int csel = lane >> 4;
    int arow = wid * 16 + (lane & 15);

    for (int kt = 0; kt <= qt; kt++) {
        int k0 = kt * 64;
        for (int i = tid; i < 1024; i += 128) {
            int r = i >> 4, c = i & 15;
            size_t g = (size_t)(k0 + r) * HD + c * 8;
            uint32_t o = aswz(r, c);
            cp_async16(sb + KHs + o, kh + g);
            cp_async16(sb + KLs + o, kl + g);
            cp_async16(sb + VHs + o, vh + g);
            cp_async16(sb + VLs + o, vl + g);
        }
        cp_commit();
        cp_wait0();
        __syncthreads();

        float s[8][4];
#pragma unroll
        for (int j = 0; j < 8; j++)
#pragma unroll
            for (int r = 0; r < 4; r++) s[j][r] = 0.f;

#pragma unroll
        for (int ks = 0; ks < 8; ks++) {
            int ch = 2 * ks + csel;
            uint32_t ah[4], al[4];
            ldm_x4(ah[0], ah[1], ah[2], ah[3], sb + QH + aswz(arow, ch));
            ldm_x4(al[0], al[1], al[2], al[3], sb + QL + aswz(arow, ch));
#pragma unroll
            for (int nt = 0; nt < 4; nt++) {
                int krow = nt * 16 + (lane & 15);
                uint32_t t0, t1, t2, t3, u0, u1, u2, u3;
                ldm_x4(t0, t1, t2, t3, sb + KHs + aswz(krow, ch));
                ldm_x4(u0, u1, u2, u3, sb + KLs + aswz(krow, ch));
                uint32_t bh0[2] = {t0, t2}, bh1[2] = {t1, t3};
                uint32_t bl0[2] = {u0, u2}, bl1[2] = {u1, u3};
                mma_bf16(s[2 * nt], ah, bh0);     mma_bf16(s[2 * nt + 1], ah, bh1);
                mma_bf16(s[2 * nt], al, bh0);     mma_bf16(s[2 * nt + 1], al, bh1);
                mma_bf16(s[2 * nt], ah, bl0);     mma_bf16(s[2 * nt + 1], ah, bl1);
            }
        }

        if (kt == qt) {
            int r0g = q0 + wid * 16 + grp;
#pragma unroll
            for (int j = 0; j < 8; j++) {
                int cb = k0 + j * 8 + 2 * qid;
                if (cb > r0g)         s[j][0] = -1e30f;
                if (cb + 1 > r0g)     s[j][1] = -1e30f;
                if (cb > r0g + 8)     s[j][2] = -1e30f;
                if (cb + 1 > r0g + 8) s[j][3] = -1e30f;
            }
        }

        float mx0 = -1e30f, mx1 = -1e30f;
#pragma unroll
        for (int j = 0; j < 8; j++) {
            mx0 = fmaxf(mx0, fmaxf(s[j][0], s[j][1]));
            mx1 = fmaxf(mx1, fmaxf(s[j][2], s[j][3]));
        }
        mx0 = fmaxf(mx0, __shfl_xor_sync(0xffffffffu, mx0, 1));
        mx0 = fmaxf(mx0, __shfl_xor_sync(0xffffffffu, mx0, 2));
        mx1 = fmaxf(mx1, __shfl_xor_sync(0xffffffffu, mx1, 1));
        mx1 = fmaxf(mx1, __shfl_xor_sync(0xffffffffu, mx1, 2));
        float nm0 = fmaxf(m0, mx0), nm1 = fmaxf(m1, mx1);
        float f0 = __expf(m0 - nm0), f1 = __expf(m1 - nm1);
        m0 = nm0; m1 = nm1;
        float sum0 = 0.f, sum1 = 0.f;
#pragma unroll
        for (int j = 0; j < 8; j++) {
            s[j][0] = __expf(s[j][0] - nm0);
            s[j][1] = __expf(s[j][1] - nm0);
            s[j][2] = __expf(s[j][2] - nm1);
            s[j][3] = __expf(s[j][3] - nm1);
            sum0 += s[j][0] + s[j][1];
            sum1 += s[j][2] + s[j][3];
        }
        sum0 += __shfl_xor_sync(0xffffffffu, sum0, 1);
        sum0 += __shfl_xor_sync(0xffffffffu, sum0, 2);
        sum1 += __shfl_xor_sync(0xffffffffu, sum1, 1);
        sum1 += __shfl_xor_sync(0xffffffffu, sum1, 2);
        l0 = l0 * f0 + sum0;
        l1 = l1 * f1 + sum1;
#pragma unroll
        for (int t = 0; t < 16; t++) {
            O[t][0] *= f0; O[t][1] *= f0; O[t][2] *= f1; O[t][3] *= f1;
        }

#pragma unroll
        for (int kc = 0; kc < 4; kc++) {
            float p00 = s[2 * kc][0], p01 = s[2 * kc][1], p02 = s[2 * kc][2], p03 = s[2 * kc][3];
            float p10 = s[2 * kc + 1][0], p11 = s[2 * kc + 1][1], p12 = s[2 * kc + 1][2], p13 = s[2 * kc + 1][3];
            uint32_t ph[4], pl[4];
            ph[0] = packbf(p00, p01); ph[1] = packbf(p02, p03);
            ph[2] = packbf(p10, p11); ph[3] = packbf(p12, p13);
            float q00 = p00 - __bfloat162float(__float2bfloat16(p00));
            float q01 = p01 - __bfloat162float(__float2bfloat16(p01));
            float q02 = p02 - __bfloat162float(__float2bfloat16(p02));
            float q03 = p03 - __bfloat162float(__float2bfloat16(p03));
            float q10 = p10 - __bfloat162float(__float2bfloat16(p10));
            float q11 = p11 - __bfloat162float(__float2bfloat16(p11));
            float q12 = p12 - __bfloat162float(__float2bfloat16(p12));
            float q13 = p13 - __bfloat162float(__float2bfloat16(p13));
            pl[0] = packbf(q00, q01); pl[1] = packbf(q02, q03);
            pl[2] = packbf(q10, q11); pl[3] = packbf(q12, q13);

            int vrow = kc * 16 + ((lane >> 3) & 1) * 8 + (lane & 7);
#pragma unroll
            for (int dn = 0; dn < 8; dn++) {
                int ch2 = 2 * dn + csel;
                uint32_t t0, t1, t2, t3, u0, u1, u2, u3;
                ldmt_x4(t0, t1, t2, t3, sb + VHs + aswz(vrow, ch2));
                ldmt_x4(u0, u1, u2, u3, sb + VLs + aswz(vrow, ch2));
                uint32_t bh0[2] = {t0, t1}, bh1[2] = {t2, t3};
                uint32_t bl0[2] = {u0, u1}, bl1[2] = {u2, u3};
                mma_bf16(O[2 * dn], ph, bh0);     mma_bf16(O[2 * dn + 1], ph, bh1);
                mma_bf16(O[2 * dn], pl, bh0);     mma_bf16(O[2 * dn + 1], pl, bh1);
                mma_bf16(O[2 * dn], ph, bl0);     mma_bf16(O[2 * dn + 1], ph, bl1);
            }
        }
        __syncthreads();
    }

    float i0 = 1.0f / l0, i1 = 1.0f / l1;
    int r0g = q0 + wid * 16 + grp;
    size_t base0 = ((size_t)(b * T_) + r0g) * C_ + h * HD;
    size_t base1 = base0 + (size_t)8 * C_;
#pragma unroll
    for (int t = 0; t < 16; t++) {
        int col = t * 8 + 2 * qid;
        float v0 = O[t][0] * i0, v1 = O[t][1] * i0;
        float v2 = O[t][2] * i1, v3 = O[t][3] * i1;
        float h0 = __bfloat162float(__float2bfloat16(v0));
        float h1 = __bfloat162float(__float2bfloat16(v1));
        float h2 = __bfloat162float(__float2bfloat16(v2));
        float h3 = __bfloat162float(__float2bfloat16(v3));
        *(uint32_t*)(g_yhi + base0 + col) = packbf(v0, v1);
        *(uint32_t*)(g_ylo + base0 + col) = packbf(v0 - h0, v1 - h1);
        *(uint32_t*)(g_yhi + base1 + col) = packbf(v2, v3);
        *(uint32_t*)(g_ylo + base1 + col) = packbf(v2 - h2, v3 - h3);
    }
}

// ---------------------------------------------------------------------------
// Launch pipeline
// ---------------------------------------------------------------------------
extern "C" void kernel_launch(void* const* d_in, const int* in_sizes, int n_in,
                              void* d_out, int out_size)
{
    const float* x      = (const float*)d_in[0];
    const float* w_attn = (const float*)d_in[1];
    const float* w_proj = (const float*)d_in[2];
    const float* cosb   = (const float*)d_in[3];
    const float* sinb   = (const float*)d_in[4];
    float* out = (float*)d_out;

    void *p_qkv, *p_xhi, *p_xlo, *p_wahi, *p_walo, *p_wphi, *p_wplo, *p_yhi, *p_ylo;
    cudaGetSymbolAddress(&p_qkv, g_qkv);
    cudaGetSymbolAddress(&p_xhi, g_xhi);  cudaGetSymbolAddress(&p_xlo, g_xlo);
    cudaGetSymbolAddress(&p_wahi, g_wahi); cudaGetSymbolAddress(&p_walo, g_walo);
    cudaGetSymbolAddress(&p_wphi, g_wphi); cudaGetSymbolAddress(&p_wplo, g_wplo);
    cudaGetSymbolAddress(&p_yhi, g_yhi);  cudaGetSymbolAddress(&p_ylo, g_ylo);

    cudaFuncSetAttribute(attn_mma_kernel, cudaFuncAttributeMaxDynamicSharedMemorySize, ATT_SMEM);

    int n4x = (B_ * T_ * C_) / 4;
    split_bf16_kernel<<<(n4x + 255) / 256, 256>>>(x, (__nv_bfloat16*)p_xhi, (__nv_bfloat16*)p_xlo, n4x);
    int n4wa = (QKV_DIM * C_) / 4;
    split_bf16_kernel<<<(n4wa + 255) / 256, 256>>>(w_attn, (__nv_bfloat16*)p_wahi, (__nv_bfloat16*)p_walo, n4wa);
    int n4wp = (C_ * C_) / 4;
    split_bf16_kernel<<<(n4wp + 255) / 256, 256>>>(w_proj, (__nv_bfloat16*)p_wphi, (__nv_bfloat16*)p_wplo, n4wp);

    dim3 g1(QKV_DIM / 128, (B_ * T_) / 128);
    gemm_mma_kernel<<<g1, 128>>>(
        (const __nv_bfloat16*)p_xhi, (const __nv_bfloat16*)p_xlo,
        (const __nv_bfloat16*)p_wahi, (const __nv_bfloat16*)p_walo,
        (float*)p_qkv, B_ * T_, QKV_DIM, C_);

    rope_rms_kernel<<<B_ * T_, 256>>>(cosb, sinb);

    dim3 ga(T_ / 64, NH, B_);
    attn_mma_kernel<<<ga, 128, ATT_SMEM>>>();

    dim3 g2(C_ / 128, (B_ * T_) / 128);
    gemm_mma_kernel<<<g2, 128>>>(
        (const __nv_bfloat16*)p_yhi, (const __nv_bfloat16*)p_ylo,
        (const __nv_bfloat16*)p_wphi, (const __nv_bfloat16*)p_wplo,
        out, B_ * T_, C_, C_);
}

// round 7
// speedup vs baseline: 3.5023x; 1.0733x over previous
#include <cuda_runtime.h>
#include <cuda_bf16.h>
#include <cstdint>
#include <math.h>

// Problem constants
#define B_   2
#define T_   2048
#define C_   2048
#define NH   16
#define NKV  8
#define HD   128
#define KVD  (NKV*HD)          // 1024
#define QKV_DIM (C_ + 2*KVD)   // 4096
#define EPS_ 1.1920929e-07f
#define SCALE_ 0.08838834764831845f   // 1/sqrt(128)

// ---------------- scratch (static device globals; allocation-free) ----------
__device__ float g_qkv[(size_t)B_*T_*QKV_DIM];   // 64 MB
// bf16 hi/lo planes
__device__ __nv_bfloat16 g_xhi[(size_t)B_*T_*C_];
__device__ __nv_bfloat16 g_xlo[(size_t)B_*T_*C_];
__device__ __nv_bfloat16 g_wahi[(size_t)QKV_DIM*C_];
__device__ __nv_bfloat16 g_walo[(size_t)QKV_DIM*C_];
__device__ __nv_bfloat16 g_wphi[(size_t)C_*C_];
__device__ __nv_bfloat16 g_wplo[(size_t)C_*C_];
__device__ __nv_bfloat16 g_yhi[(size_t)B_*T_*C_];
__device__ __nv_bfloat16 g_ylo[(size_t)B_*T_*C_];
// q/k/v hi/lo planes, layouts q:[b,h,t,d] k,v:[b,kvh,t,d]
__device__ __nv_bfloat16 g_qhi[(size_t)B_*NH*T_*HD];
__device__ __nv_bfloat16 g_qlo[(size_t)B_*NH*T_*HD];
__device__ __nv_bfloat16 g_khi[(size_t)B_*NKV*T_*HD];
__device__ __nv_bfloat16 g_klo[(size_t)B_*NKV*T_*HD];
__device__ __nv_bfloat16 g_vhi[(size_t)B_*NKV*T_*HD];
__device__ __nv_bfloat16 g_vlo[(size_t)B_*NKV*T_*HD];

// ---------------------------------------------------------------------------
// helpers
// ---------------------------------------------------------------------------
__device__ __forceinline__ uint32_t smem_u32(const void* p) {
    uint32_t a;
    asm("{ .reg .u64 t; cvta.to.shared.u64 t, %1; cvt.u32.u64 %0, t; }" : "=r"(a) : "l"(p));
    return a;
}
__device__ __forceinline__ void cp_async16(uint32_t dst, const void* src) {
    asm volatile("cp.async.cg.shared.global [%0], [%1], 16;" :: "r"(dst), "l"(src));
}
__device__ __forceinline__ void cp_commit() { asm volatile("cp.async.commit_group;"); }
__device__ __forceinline__ void cp_wait1() { asm volatile("cp.async.wait_group 1;"); }
__device__ __forceinline__ void cp_wait0() { asm volatile("cp.async.wait_group 0;"); }
__device__ __forceinline__ void ldm_x4(uint32_t& r0, uint32_t& r1, uint32_t& r2, uint32_t& r3, uint32_t a) {
    asm volatile("ldmatrix.sync.aligned.m8n8.x4.shared.b16 {%0,%1,%2,%3}, [%4];"
                 : "=r"(r0), "=r"(r1), "=r"(r2), "=r"(r3) : "r"(a));
}
__device__ __forceinline__ void ldmt_x4(uint32_t& r0, uint32_t& r1, uint32_t& r2, uint32_t& r3, uint32_t a) {
    asm volatile("ldmatrix.sync.aligned.m8n8.x4.trans.shared.b16 {%0,%1,%2,%3}, [%4];"
                 : "=r"(r0), "=r"(r1), "=r"(r2), "=r"(r3) : "r"(a));
}
__device__ __forceinline__ void mma_bf16(float* d, const uint32_t* a, const uint32_t* b) {
    asm volatile(
        "mma.sync.aligned.m16n8k16.row.col.f32.bf16.bf16.f32 "
        "{%0,%1,%2,%3}, {%4,%5,%6,%7}, {%8,%9}, {%0,%1,%2,%3};"
        : "+f"(d[0]), "+f"(d[1]), "+f"(d[2]), "+f"(d[3])
        : "r"(a[0]), "r"(a[1]), "r"(a[2]), "r"(a[3]), "r"(b[0]), "r"(b[1]));
}
__device__ __forceinline__ uint32_t packbf(float a, float b) {
    uint32_t r;
    asm("cvt.rn.bf16x2.f32 %0, %1, %2;" : "=r"(r) : "f"(b), "f"(a));
    return r;
}
// gemm smem swizzle (64B rows, 4 chunks of 16B)
__device__ __forceinline__ uint32_t swz(int r, int c) {
    return (uint32_t)(r * 64 + ((c ^ ((r >> 1) & 3)) << 4));
}
// attention smem swizzle (256B rows, 16 chunks of 16B)
__device__ __forceinline__ uint32_t aswz(int r, int c) {
    return (uint32_t)(r * 256 + (((c ^ r) & 7) | (c & 8)) * 16);
}

// ---------------------------------------------------------------------------
// split fp32 -> (hi, lo) bf16 planes
// ---------------------------------------------------------------------------
__global__ __launch_bounds__(256) void split_bf16_kernel(
    const float* __restrict__ in, __nv_bfloat16* __restrict__ hi,
    __nv_bfloat16* __restrict__ lo, int n4)
{
    int i = blockIdx.x * blockDim.x + threadIdx.x;
    if (i >= n4) return;
    float4 v = ((const float4*)in)[i];
    __nv_bfloat16 h0 = __float2bfloat16(v.x);
    __nv_bfloat16 h1 = __float2bfloat16(v.y);
    __nv_bfloat16 h2 = __float2bfloat16(v.z);
    __nv_bfloat16 h3 = __float2bfloat16(v.w);
    __nv_bfloat16 l0 = __float2bfloat16(v.x - __bfloat162float(h0));
    __nv_bfloat16 l1 = __float2bfloat16(v.y - __bfloat162float(h1));
    __nv_bfloat16 l2 = __float2bfloat16(v.z - __bfloat162float(h2));
    __nv_bfloat16 l3 = __float2bfloat16(v.w - __bfloat162float(h3));
    __nv_bfloat162 ha, hb, la, lb;
    ha.x = h0; ha.y = h1; hb.x = h2; hb.y = h3;
    la.x = l0; la.y = l1; lb.x = l2; lb.y = l3;
    ((__nv_bfloat162*)hi)[2 * i]     = ha;
    ((__nv_bfloat162*)hi)[2 * i + 1] = hb;
    ((__nv_bfloat162*)lo)[2 * i]     = la;
    ((__nv_bfloat162*)lo)[2 * i + 1] = lb;
}

// ---------------------------------------------------------------------------
// Fused hi/lo bf16 split GEMM (NT) via mma.sync, SINGLE k-sweep.
// Per k-chunk: load Ahi,Alo,Bhi,Blo tiles once; do 3 MMA groups
// (hi*hi + lo*hi + hi*lo) into the same fp32 accumulators.
// CTA tile 128x128, BK=32, 128 threads = 4 warps (2x2), warp tile 64x64.
// 3-stage cp.async pipeline (96KB dynamic smem), one barrier per chunk.
// ---------------------------------------------------------------------------
#define GSTAGE 32768
#define GSMEM (3 * GSTAGE)

__global__ __launch_bounds__(128, 2) void gemm_mma_kernel(
    const __nv_bfloat16* __restrict__ Ahi, const __nv_bfloat16* __restrict__ Alo,
    const __nv_bfloat16* __restrict__ Bhi, const __nv_bfloat16* __restrict__ Blo,
    float* __restrict__ C, int M, int N, int K)
{
    extern __shared__ unsigned char gsm_raw[];
    uint32_t sb = smem_u32(gsm_raw);

    int tid = threadIdx.x;
    int wid = tid >> 5, lane = tid & 31;
    int wm = wid >> 1, wn = wid & 1;      // warp grid 2x2
    int m0 = blockIdx.y * 128, n0 = blockIdx.x * 128;
    int grp = lane >> 2, qid = lane & 3;

    float acc[4][8][4];
#pragma unroll
    for (int mi = 0; mi < 4; mi++)
#pragma unroll
        for (int ni = 0; ni < 8; ni++)
#pragma unroll
            for (int r = 0; r < 4; r++) acc[mi][ni][r] = 0.f;

    int nch = K >> 5;   // BK=32 chunks (single sweep)

    // per-thread: 4 positions x 4 tiles = 16 cp.async per stage
    auto issue = [&](int c) {
        int kofs = c << 5;
        int s = c % 3;
        uint32_t st = sb + s * GSTAGE;
#pragma unroll
        for (int it = 0; it < 4; it++) {
            int idx = tid + it * 128;           // 0..511
            int r = idx >> 2, ch = idx & 3;
            uint32_t o = swz(r, ch);
            size_t ga = (size_t)(m0 + r) * K + kofs + ch * 8;
            size_t gb = (size_t)(n0 + r) * K + kofs + ch * 8;
            cp_async16(st + o,         Ahi + ga);
            cp_async16(st + 8192 + o,  Alo + ga);
            cp_async16(st + 16384 + o, Bhi + gb);
            cp_async16(st + 24576 + o, Blo + gb);
        }
        cp_commit();
    };

    issue(0);
    issue(1);

    int lrow_add = (lane & 7) + (((lane >> 3) & 1) << 3);
    int lchunk_add = lane >> 4;

    for (int c = 0; c < nch; c++) {
        if (c + 1 < nch) cp_wait1(); else cp_wait0();
        __syncthreads();
        if (c + 2 < nch) issue(c + 2);

        int s = c % 3;
        uint32_t aH = sb + s * GSTAGE;
        uint32_t aL = aH + 8192;
        uint32_t bH = aH + 16384;
        uint32_t bL = aH + 24576;

#pragma unroll
        for (int ks = 0; ks < 2; ks++) {
            int cbase = ks * 2 + lchunk_add;
            uint32_t ahi[4][4], alo[4][4];
#pragma unroll
            for (int mi = 0; mi < 4; mi++) {
                int row = wm * 64 + mi * 16 + lrow_add;
                uint32_t o = swz(row, cbase);
                ldm_x4(ahi[mi][0], ahi[mi][1], ahi[mi][2], ahi[mi][3], aH + o);
                ldm_x4(alo[mi][0], alo[mi][1], alo[mi][2], alo[mi][3], aL + o);
            }
#pragma unroll
            for (int nh = 0; nh < 2; nh++) {
                uint32_t bh[4][2], bl[4][2];
#pragma unroll
                for (int p = 0; p < 2; p++) {
                    int row = wn * 64 + nh * 32 + p * 16 + lrow_add;
                    uint32_t o = swz(row, cbase);
                    uint32_t t0, t1, t2, t3;
                    ldm_x4(t0, t1, t2, t3, bH + o);
                    bh[p * 2][0] = t0;     bh[p * 2][1] = t2;
                    bh[p * 2 + 1][0] = t1; bh[p * 2 + 1][1] = t3;
                    uint32_t u0, u1, u2, u3;
                    ldm_x4(u0, u1, u2, u3, bL + o);
                    bl[p * 2][0] = u0;     bl[p * 2][1] = u2;
                    bl[p * 2 + 1][0] = u1; bl[p * 2 + 1][1] = u3;
                }
#pragma unroll
                for (int mi = 0; mi < 4; mi++)
#pragma unroll
                    for (int ni = 0; ni < 4; ni++) {
                        float* d = acc[mi][nh * 4 + ni];
                        mma_bf16(d, ahi[mi], bh[ni]);
                        mma_bf16(d, alo[mi], bh[ni]);
                        mma_bf16(d, ahi[mi], bl[ni]);
                    }
            }
        }
    }

    // epilogue
#pragma unroll
    for (int mi = 0; mi < 4; mi++) {
        int rbase = m0 + wm * 64 + mi * 16 + grp;
#pragma unroll
        for (int ni = 0; ni < 8; ni++) {
            int col = n0 + wn * 64 + ni * 8 + qid * 2;
            float* p0 = C + (size_t)rbase * N + col;
            float* p1 = C + (size_t)(rbase + 8) * N + col;
            p0[0] = acc[mi][ni][0]; p0[1] = acc[mi][ni][1];
            p1[0] = acc[mi][ni][2]; p1[1] = acc[mi][ni][3];
        }
    }
}

// ---------------------------------------------------------------------------
// RoPE + RMSnorm + split to bf16 hi/lo planes (q pre-scaled by 1/sqrt(d))
// ---------------------------------------------------------------------------
__global__ __launch_bounds__(256) void rope_rms_kernel(
    const float* __restrict__ cosb, const float* __restrict__ sinb)
{
    int bt = blockIdx.x;
    int b = bt / T_, t = bt % T_;
    int warp = threadIdx.x >> 5, lane = threadIdx.x & 31;
    const float* base = g_qkv + (size_t)bt * QKV_DIM;

    float c0 = cosb[t * 64 + lane], c1 = cosb[t * 64 + lane + 32];
    float s0 = sinb[t * 64 + lane], s1 = sinb[t * 64 + lane + 32];

    for (int hh = warp; hh < NH + NKV; hh += 8) {
        const float* src;
        __nv_bfloat16 *dhi, *dlo;
        float scl;
        if (hh < NH) {
            src = base + hh * HD;
            size_t o = ((size_t)(b * NH + hh) * T_ + t) * HD;
            dhi = g_qhi + o; dlo = g_qlo + o; scl = SCALE_;
        } else {
            int kv = hh - NH;
            src = base + C_ + kv * HD;
            size_t o = ((size_t)(b * NKV + kv) * T_ + t) * HD;
            dhi = g_khi + o; dlo = g_klo + o; scl = 1.0f;
        }
        float v0 = src[lane], v1 = src[lane + 32], v2 = src[lane + 64], v3 = src[lane + 96];
        float y0 =  v0 * c0 + v2 * s0;
        float y2 = -v0 * s0 + v2 * c0;
        float y1 =  v1 * c1 + v3 * s1;
        float y3 = -v1 * s1 + v3 * c1;
        float ss = y0 * y0 + y1 * y1 + y2 * y2 + y3 * y3;
#pragma unroll
        for (int o = 16; o > 0; o >>= 1) ss += __shfl_xor_sync(0xffffffffu, ss, o);
        float r = rsqrtf(ss * (1.0f / HD) + EPS_) * scl;
        float w0 = y0 * r, w1 = y1 * r, w2 = y2 * r, w3 = y3 * r;
        __nv_bfloat16 h0 = __float2bfloat16(w0), h1 = __float2bfloat16(w1);
        __nv_bfloat16 h2 = __float2bfloat16(w2), h3 = __float2bfloat16(w3);
        dhi[lane]      = h0; dlo[lane]      = __float2bfloat16(w0 - __bfloat162float(h0));
        dhi[lane + 32] = h1; dlo[lane + 32] = __float2bfloat16(w1 - __bfloat162float(h1));
        dhi[lane + 64] = h2; dlo[lane + 64] = __float2bfloat16(w2 - __bfloat162float(h2));
        dhi[lane + 96] = h3; dlo[lane + 96] = __float2bfloat16(w3 - __bfloat162float(h3));
    }
    // V split
    {
        int kv = warp;
        const float4* src = (const float4*)(base + C_ + KVD + kv * HD);
        float4 v = src[lane];
        size_t o = ((size_t)(b * NKV + kv) * T_ + t) * HD + 4 * lane;
        __nv_bfloat16 h0 = __float2bfloat16(v.x), h1 = __float2bfloat16(v.y);
        __nv_bfloat16 h2 = __float2bfloat16(v.z), h3 = __float2bfloat16(v.w);
        __nv_bfloat162 ha, hb, la, lb;
        ha.x = h0; ha.y = h1; hb.x = h2; hb.y = h3;
        la.x = __float2bfloat16(v.x - __bfloat162float(h0));
        la.y = __float2bfloat16(v.y - __bfloat162float(h1));
        lb.x = __float2bfloat16(v.z - __bfloat162float(h2));
        lb.y = __float2bfloat16(v.w - __bfloat162float(h3));
        *(__nv_bfloat162*)(g_vhi + o)     = ha;
        *(__nv_bfloat162*)(g_vhi + o + 2) = hb;
        *(__nv_bfloat162*)(g_vlo + o)     = la;
        *(__nv_bfloat162*)(g_vlo + o + 2) = lb;
    }
}

// ---------------------------------------------------------------------------
// Tensor-core flash attention, causal, GQA, bf16 hi/lo 3-pass (unchanged — passed)
// ---------------------------------------------------------------------------
#define ATT_SMEM (6 * 16384)

__global__ __launch_bounds__(128) void attn_mma_kernel()
{
    extern __shared__ unsigned char attn_smem_raw[];
    uint32_t sb = smem_u32(attn_smem_raw);
    const uint32_t QH = 0, QL = 16384, KHs = 32768, KLs = 49152, VHs = 65536, VLs = 81920;

    int qt = blockIdx.x, h = blockIdx.y, b = blockIdx.z;
    int kvh = h >> 1;
    int tid = threadIdx.x, wid = tid >> 5, lane = tid & 31;
    int grp = lane >> 2, qid = lane & 3;
    int q0 = qt * 64;

    const __nv_bfloat16* qh = g_qhi + ((size_t)(b * NH + h) * T_ + q0) * HD;
    const __nv_bfloat16* ql = g_qlo + ((size_t)(b * NH + h) * T_ + q0) * HD;
    const __nv_bfloat16* kh = g_khi + ((size_t)(b * NKV + kvh) * T_) * HD;
    const __nv_bfloat16* kl = g_klo + ((size_t)(b * NKV + kvh) * T_) * HD;
    const __nv_bfloat16* vh = g_vhi + ((size_t)(b * NKV + kvh) * T_) * HD;
    const __nv_bfloat16* vl = g_vlo + ((size_t)(b * NKV + kvh) * T_) * HD;

    for (int i = tid; i < 1024; i += 128) {
        int r = i >> 4, c = i & 15;
        uint32_t o = aswz(r, c);
        cp_async16(sb + QH + o, qh + (size_t)r * HD + c * 8);
        cp_async16(sb + QL + o, ql + (size_t)r * HD + c * 8);
    }
    cp_commit();

    float O[16][4];
#pragma unroll
    for (int t = 0; t < 16; t++)
#pragma unroll
        for (int r = 0; r < 4; r++) O[t][r] = 0.f;
    float m0 = -1e30f, m1 = -1e30f, l0 = 0.f, l1 = 0.f;

    int csel = lane >> 4;
    int arow = wid * 16 + (lane & 15);

    for (int kt = 0; kt <= qt; kt++) {
        int k0 = kt * 64;
        for (int i = tid; i < 1024; i += 128) {
            int r = i >> 4, c = i & 15;
            size_t g = (size_t)(k0 + r) * HD + c * 8;
            uint32_t o = aswz(r, c);
            cp_async16(sb + KHs + o, kh + g);
            cp_async16(sb + KLs + o, kl + g);
            cp_async16(sb + VHs + o, vh + g);
            cp_async16(sb + VLs + o, vl + g);
        }
        cp_commit();
        cp_wait0();
        __syncthreads();

        float s[8][4];
#pragma unroll
        for (int j = 0; j < 8; j++)
#pragma unroll
            for (int r = 0; r < 4; r++) s[j][r] = 0.f;

#pragma unroll
        for (int ks = 0; ks < 8; ks++) {
            int ch = 2 * ks + csel;
            uint32_t ah[4], al[4];
            ldm_x4(ah[0], ah[1], ah[2], ah[3], sb + QH + aswz(arow, ch));
            ldm_x4(al[0], al[1], al[2], al[3], sb + QL + aswz(arow, ch));
#pragma unroll
            for (int nt = 0; nt < 4; nt++) {
                int krow = nt * 16 + (lane & 15);
                uint32_t t0, t1, t2, t3, u0, u1, u2, u3;
                ldm_x4(t0, t1, t2, t3, sb + KHs + aswz(krow, ch));
                ldm_x4(u0, u1, u2, u3, sb + KLs + aswz(krow, ch));
                uint32_t bh0[2] = {t0, t2}, bh1[2] = {t1, t3};
                uint32_t bl0[2] = {u0, u2}, bl1[2] = {u1, u3};
                mma_bf16(s[2 * nt], ah, bh0);     mma_bf16(s[2 * nt + 1], ah, bh1);
                mma_bf16(s[2 * nt], al, bh0);     mma_bf16(s[2 * nt + 1], al, bh1);
                mma_bf16(s[2 * nt], ah, bl0);     mma_bf16(s[2 * nt + 1], ah, bl1);
            }
        }

        if (kt == qt) {
            int r0g = q0 + wid * 16 + grp;
#pragma unroll
            for (int j = 0; j < 8; j++) {
                int cb = k0 + j * 8 + 2 * qid;
                if (cb > r0g)         s[j][0] = -1e30f;
                if (cb + 1 > r0g)     s[j][1] = -1e30f;
                if (cb > r0g + 8)     s[j][2] = -1e30f;
                if (cb + 1 > r0g + 8) s[j][3] = -1e30f;
            }
        }

        float mx0 = -1e30f, mx1 = -1e30f;
#pragma unroll
        for (int j = 0; j < 8; j++) {
            mx0 = fmaxf(mx0, fmaxf(s[j][0], s[j][1]));
            mx1 = fmaxf(mx1, fmaxf(s[j][2], s[j][3]));
        }
        mx0 = fmaxf(mx0, __shfl_xor_sync(0xffffffffu, mx0, 1));
        mx0 = fmaxf(mx0, __shfl_xor_sync(0xffffffffu, mx0, 2));
        mx1 = fmaxf(mx1, __shfl_xor_sync(0xffffffffu, mx1, 1));
        mx1 = fmaxf(mx1, __shfl_xor_sync(0xffffffffu, mx1, 2));
        float nm0 = fmaxf(m0, mx0), nm1 = fmaxf(m1, mx1);
        float f0 = __expf(m0 - nm0), f1 = __expf(m1 - nm1);
        m0 = nm0; m1 = nm1;
        float sum0 = 0.f, sum1 = 0.f;
#pragma unroll
        for (int j = 0; j < 8; j++) {
            s[j][0] = __expf(s[j][0] - nm0);
            s[j][1] = __expf(s[j][1] - nm0);
            s[j][2] = __expf(s[j][2] - nm1);
            s[j][3] = __expf(s[j][3] - nm1);
            sum0 += s[j][0] + s[j][1];
            sum1 += s[j][2] + s[j][3];
        }
        sum0 += __shfl_xor_sync(0xffffffffu, sum0, 1);
        sum0 += __shfl_xor_sync(0xffffffffu, sum0, 2);
        sum1 += __shfl_xor_sync(0xffffffffu, sum1, 1);
        sum1 += __shfl_xor_sync(0xffffffffu, sum1, 2);
        l0 = l0 * f0 + sum0;
        l1 = l1 * f1 + sum1;
#pragma unroll
        for (int t = 0; t < 16; t++) {
            O[t][0] *= f0; O[t][1] *= f0; O[t][2] *= f1; O[t][3] *= f1;
        }

#pragma unroll
        for (int kc = 0; kc < 4; kc++) {
            float p00 = s[2 * kc][0], p01 = s[2 * kc][1], p02 = s[2 * kc][2], p03 = s[2 * kc][3];
            float p10 = s[2 * kc + 1][0], p11 = s[2 * kc + 1][1], p12 = s[2 * kc + 1][2], p13 = s[2 * kc + 1][3];
            uint32_t ph[4], pl[4];
            ph[0] = packbf(p00, p01); ph[1] = packbf(p02, p03);
            ph[2] = packbf(p10, p11); ph[3] = packbf(p12, p13);
            float q00 = p00 - __bfloat162float(__float2bfloat16(p00));
            float q01 = p01 - __bfloat162float(__float2bfloat16(p01));
            float q02 = p02 - __bfloat162float(__float2bfloat16(p02));
            float q03 = p03 - __bfloat162float(__float2bfloat16(p03));
            float q10 = p10 - __bfloat162float(__float2bfloat16(p10));
            float q11 = p11 - __bfloat162float(__float2bfloat16(p11));
            float q12 = p12 - __bfloat162float(__float2bfloat16(p12));
            float q13 = p13 - __bfloat162float(__float2bfloat16(p13));
            pl[0] = packbf(q00, q01); pl[1] = packbf(q02, q03);
            pl[2] = packbf(q10, q11); pl[3] = packbf(q12, q13);

            int vrow = kc * 16 + ((lane >> 3) & 1) * 8 + (lane & 7);
#pragma unroll
            for (int dn = 0; dn < 8; dn++) {
                int ch2 = 2 * dn + csel;
                uint32_t t0, t1, t2, t3, u0, u1, u2, u3;
                ldmt_x4(t0, t1, t2, t3, sb + VHs + aswz(vrow, ch2));
                ldmt_x4(u0, u1, u2, u3, sb + VLs + aswz(vrow, ch2));
                uint32_t bh0[2] = {t0, t1}, bh1[2] = {t2, t3};
                uint32_t bl0[2] = {u0, u1}, bl1[2] = {u2, u3};
                mma_bf16(O[2 * dn], ph, bh0);     mma_bf16(O[2 * dn + 1], ph, bh1);
                mma_bf16(O[2 * dn], pl, bh0);     mma_bf16(O[2 * dn + 1], pl, bh1);
                mma_bf16(O[2 * dn], ph, bl0);     mma_bf16(O[2 * dn + 1], ph, bl1);
            }
        }
        __syncthreads();
    }

    float i0 = 1.0f / l0, i1 = 1.0f / l1;
    int r0g = q0 + wid * 16 + grp;
    size_t base0 = ((size_t)(b * T_) + r0g) * C_ + h * HD;
    size_t base1 = base0 + (size_t)8 * C_;
#pragma unroll
    for (int t = 0; t < 16; t++) {
        int col = t * 8 + 2 * qid;
        float v0 = O[t][0] * i0, v1 = O[t][1] * i0;
        float v2 = O[t][2] * i1, v3 = O[t][3] * i1;
        float h0 = __bfloat162float(__float2bfloat16(v0));
        float h1 = __bfloat162float(__float2bfloat16(v1));
        float h2 = __bfloat162float(__float2bfloat16(v2));
        float h3 = __bfloat162float(__float2bfloat16(v3));
        *(uint32_t*)(g_yhi + base0 + col) = packbf(v0, v1);
        *(uint32_t*)(g_ylo + base0 + col) = packbf(v0 - h0, v1 - h1);
        *(uint32_t*)(g_yhi + base1 + col) = packbf(v2, v3);
        *(uint32_t*)(g_ylo + base1 + col) = packbf(v2 - h2, v3 - h3);
    }
}

// ---------------------------------------------------------------------------
// Launch pipeline
// ---------------------------------------------------------------------------
extern "C" void kernel_launch(void* const* d_in, const int* in_sizes, int n_in,
                              void* d_out, int out_size)
{
    const float* x      = (const float*)d_in[0];
    const float* w_attn = (const float*)d_in[1];
    const float* w_proj = (const float*)d_in[2];
    const float* cosb   = (const float*)d_in[3];
    const float* sinb   = (const float*)d_in[4];
    float* out = (float*)d_out;

    void *p_qkv, *p_xhi, *p_xlo, *p_wahi, *p_walo, *p_wphi, *p_wplo, *p_yhi, *p_ylo;
    cudaGetSymbolAddress(&p_qkv, g_qkv);
    cudaGetSymbolAddress(&p_xhi, g_xhi);  cudaGetSymbolAddress(&p_xlo, g_xlo);
    cudaGetSymbolAddress(&p_wahi, g_wahi); cudaGetSymbolAddress(&p_walo, g_walo);
    cudaGetSymbolAddress(&p_wphi, g_wphi); cudaGetSymbolAddress(&p_wplo, g_wplo);
    cudaGetSymbolAddress(&p_yhi, g_yhi);  cudaGetSymbolAddress(&p_ylo, g_ylo);

    cudaFuncSetAttribute(attn_mma_kernel, cudaFuncAttributeMaxDynamicSharedMemorySize, ATT_SMEM);
    cudaFuncSetAttribute(gemm_mma_kernel, cudaFuncAttributeMaxDynamicSharedMemorySize, GSMEM);

    int n4x = (B_ * T_ * C_) / 4;
    split_bf16_kernel<<<(n4x + 255) / 256, 256>>>(x, (__nv_bfloat16*)p_xhi, (__nv_bfloat16*)p_xlo, n4x);
    int n4wa = (QKV_DIM * C_) / 4;
    split_bf16_kernel<<<(n4wa + 255) / 256, 256>>>(w_attn, (__nv_bfloat16*)p_wahi, (__nv_bfloat16*)p_walo, n4wa);
    int n4wp = (C_ * C_) / 4;
    split_bf16_kernel<<<(n4wp + 255) / 256, 256>>>(w_proj, (__nv_bfloat16*)p_wphi, (__nv_bfloat16*)p_wplo, n4wp);

    dim3 g1(QKV_DIM / 128, (B_ * T_) / 128);
    gemm_mma_kernel<<<g1, 128, GSMEM>>>(
        (const __nv_bfloat16*)p_xhi, (const __nv_bfloat16*)p_xlo,
        (const __nv_bfloat16*)p_wahi, (const __nv_bfloat16*)p_walo,
        (float*)p_qkv, B_ * T_, QKV_DIM, C_);

    rope_rms_kernel<<<B_ * T_, 256>>>(cosb, sinb);

    dim3 ga(T_ / 64, NH, B_);
    attn_mma_kernel<<<ga, 128, ATT_SMEM>>>();

    dim3 g2(C_ / 128, (B_ * T_) / 128);
    gemm_mma_kernel<<<g2, 128, GSMEM>>>(
        (const __nv_bfloat16*)p_yhi, (const __nv_bfloat16*)p_ylo,
        (const __nv_bfloat16*)p_wphi, (const __nv_bfloat16*)p_wplo,
        out, B_ * T_, C_, C_);
}